// round 3
// baseline (speedup 1.0000x reference)
#include <cuda_runtime.h>
#include <cuda_bf16.h>
#include <cstdint>

#define N 8192
#define F 128
#define CSRW 128   // fixed CSR row width; max in-degree ~60 for Binomial(8192, 32/8192)

// ---------------- scratch (static device globals; no allocation) ----------
__device__ float g_Z[N * F];        // dis-scaled GEMM output (SpMM input)
__device__ float g_H1[N * F];       // layer-1 activation
__device__ int   g_cnt[N];          // in-degree per dst (col-sums of A)
__device__ int   g_csr[N * CSRW];   // fixed-slot CSR: row i at [i*CSRW, i*CSRW+cnt[i])

// ---------------- f32x2 packed helpers ------------------------------------
__device__ __forceinline__ uint64_t pk2(float lo, float hi) {
    uint64_t r;
    asm("mov.b64 %0, {%1, %2};" : "=l"(r) : "f"(lo), "f"(hi));
    return r;
}
__device__ __forceinline__ uint64_t fma2(uint64_t a, uint64_t b, uint64_t c) {
    uint64_t d;
    asm("fma.rn.f32x2 %0, %1, %2, %3;" : "=l"(d) : "l"(a), "l"(b), "l"(c));
    return d;
}
__device__ __forceinline__ void upk2(uint64_t v, float& lo, float& hi) {
    asm("mov.b64 {%0, %1}, %2;" : "=f"(lo), "=f"(hi) : "l"(v));
}

// ---------------- edge extraction (one pass over A, 256MB) ----------------
__global__ void extract_kernel(const float* __restrict__ A) {
    const float4* A4 = (const float4*)A;
    int base = blockIdx.x * 2048;   // float4 units per block: 256*8
    #pragma unroll
    for (int s = 0; s < 8; s++) {
        int q = base + threadIdx.x + 256 * s;
        float4 v = A4[q];
        int idx0 = q * 4;
        float vv[4] = {v.x, v.y, v.z, v.w};
        #pragma unroll
        for (int c = 0; c < 4; c++) {
            if (vv[c] != 0.0f) {
                int idx = idx0 + c;
                int i = idx & (N - 1);   // col = dst
                int j = idx >> 13;       // row = src
                int p = atomicAdd(&g_cnt[i], 1);
                if (p < CSRW) g_csr[i * CSRW + p] = j;
            }
        }
    }
}

// ---------------- dense GEMM: Z[j,:] = dis[j] * (M[j,:] @ W) ---------------
// Grid 512, block 128. Tile: 16 rows x 128 cols. Thread: 4 rows x 4 cols,
// packed as 8 f32x2 accumulators (row pairs). W prefetched one k ahead.
#define XS_STRIDE 18   // even (8B-aligned LDS.64) and conflict-light on fill
__global__ void gemm_kernel(const float* __restrict__ M,
                            const float* __restrict__ W,
                            float* __restrict__ out) {
    __shared__ float Xs[128 * XS_STRIDE];   // Xs[k*XS_STRIDE + r], r in [0,16)
    int tid = threadIdx.x;
    int rowBase = blockIdx.x * 16;

    // Fill Xs transposed: Xs[k][r] = M[rowBase+r][k]; coalesced global reads.
    #pragma unroll
    for (int idx = tid; idx < 2048; idx += 128) {
        int r = idx >> 7;
        int k = idx & 127;
        Xs[k * XS_STRIDE + r] = M[(rowBase + r) * F + k];
    }
    __syncthreads();

    const float4* W4 = (const float4*)W;
    int cg = tid & 31;          // col group: cols [4*cg, 4*cg+4)
    int r0 = (tid >> 5) * 4;    // 0,4,8,12

    uint64_t acc[2][4];
    #pragma unroll
    for (int p = 0; p < 2; p++)
        #pragma unroll
        for (int c = 0; c < 4; c++) acc[p][c] = 0;

    float4 w = W4[cg];          // prefetch k=0
    #pragma unroll 8
    for (int k = 0; k < 128; k++) {
        float4 wc = w;
        if (k < 127) w = W4[(k + 1) * 32 + cg];
        uint64_t xp0 = *(const uint64_t*)&Xs[k * XS_STRIDE + r0];      // rows r0,r0+1
        uint64_t xp1 = *(const uint64_t*)&Xs[k * XS_STRIDE + r0 + 2];  // rows r0+2,r0+3
        uint64_t wd0 = pk2(wc.x, wc.x);
        uint64_t wd1 = pk2(wc.y, wc.y);
        uint64_t wd2 = pk2(wc.z, wc.z);
        uint64_t wd3 = pk2(wc.w, wc.w);
        acc[0][0] = fma2(xp0, wd0, acc[0][0]);
        acc[0][1] = fma2(xp0, wd1, acc[0][1]);
        acc[0][2] = fma2(xp0, wd2, acc[0][2]);
        acc[0][3] = fma2(xp0, wd3, acc[0][3]);
        acc[1][0] = fma2(xp1, wd0, acc[1][0]);
        acc[1][1] = fma2(xp1, wd1, acc[1][1]);
        acc[1][2] = fma2(xp1, wd2, acc[1][2]);
        acc[1][3] = fma2(xp1, wd3, acc[1][3]);
    }

    // Epilogue: unpack, scale by dis[row], vectorized store.
    float4* out4 = (float4*)out;
    #pragma unroll
    for (int p = 0; p < 2; p++) {
        float v0[4], v1[4];
        #pragma unroll
        for (int c = 0; c < 4; c++) upk2(acc[p][c], v0[c], v1[c]);
        int rowA = rowBase + r0 + 2 * p;
        int rowB = rowA + 1;
        float scA = rsqrtf((float)g_cnt[rowA] + 1.0f);
        float scB = rsqrtf((float)g_cnt[rowB] + 1.0f);
        out4[rowA * 32 + cg] = make_float4(v0[0] * scA, v0[1] * scA, v0[2] * scA, v0[3] * scA);
        out4[rowB * 32 + cg] = make_float4(v1[0] * scB, v1[1] * scB, v1[2] * scB, v1[3] * scB);
    }
}

// ---------------- SpMM gather: out[i,:] = relu(dis[i]*(Z[i,:]+sum Z[src,:]) + b)
__global__ void spmm_kernel(const float* __restrict__ Z,
                            const float* __restrict__ bias,
                            float* __restrict__ out) {
    __shared__ int sidx[CSRW];
    int i = blockIdx.x;
    int f = threadIdx.x;  // 128
    int cnt = g_cnt[i];
    int m = cnt < CSRW ? cnt : CSRW;

    if (f < m) sidx[f] = g_csr[i * CSRW + f];
    __syncthreads();

    float acc = Z[i * F + f];  // self-loop (I term)

    int e = 0;
    for (; e + 8 <= m; e += 8) {
        float a0 = Z[sidx[e]     * F + f];
        float a1 = Z[sidx[e + 1] * F + f];
        float a2 = Z[sidx[e + 2] * F + f];
        float a3 = Z[sidx[e + 3] * F + f];
        float a4 = Z[sidx[e + 4] * F + f];
        float a5 = Z[sidx[e + 5] * F + f];
        float a6 = Z[sidx[e + 6] * F + f];
        float a7 = Z[sidx[e + 7] * F + f];
        acc += ((a0 + a1) + (a2 + a3)) + ((a4 + a5) + (a6 + a7));
    }
    for (; e < m; e++) acc += Z[sidx[e] * F + f];

    float dis = rsqrtf((float)cnt + 1.0f);
    float r = dis * acc + bias[f];
    out[i * F + f] = fmaxf(r, 0.0f);
}

// ---------------- launch ---------------------------------------------------
extern "C" void kernel_launch(void* const* d_in, const int* in_sizes, int n_in,
                              void* d_out, int out_size) {
    const float* X  = (const float*)d_in[0];
    const float* A  = (const float*)d_in[1];
    const float* W1 = (const float*)d_in[2];
    const float* b1 = (const float*)d_in[3];
    const float* W2 = (const float*)d_in[4];
    const float* b2 = (const float*)d_in[5];
    float* out = (float*)d_out;

    float* Z;   cudaGetSymbolAddress((void**)&Z,   g_Z);
    float* H1;  cudaGetSymbolAddress((void**)&H1,  g_H1);
    int*   cnt; cudaGetSymbolAddress((void**)&cnt, g_cnt);

    cudaMemsetAsync(cnt, 0, N * sizeof(int));

    extract_kernel<<<8192, 256>>>(A);

    gemm_kernel<<<512, 128>>>(X, W1, Z);      // Z = dis .* (X @ W1)
    spmm_kernel<<<8192, 128>>>(Z, b1, H1);    // H1 = relu(An@(X@W1) + b1)

    gemm_kernel<<<512, 128>>>(H1, W2, Z);     // Z = dis .* (H1 @ W2)
    spmm_kernel<<<8192, 128>>>(Z, b2, out);   // out = relu(An@(H1@W2) + b2)
}

// round 4
// speedup vs baseline: 1.0221x; 1.0221x over previous
#include <cuda_runtime.h>
#include <cuda_bf16.h>
#include <cstdint>

#define N 8192
#define F 128
#define CSRW 128       // fixed CSR row width; max in-degree ~60 for Binomial(8192, 32/8192)
#define GEMM_ROWS 16   // rows per gemm block
#define GEMM_GRID (N / GEMM_ROWS)   // 512
#define XS_STRIDE 18   // even => 8B-aligned LDS.64; 2-way conflict on fill only

// ---------------- scratch (static device globals; no allocation) ----------
__device__ float g_Z[N * F];        // UNscaled GEMM output (SpMM input)
__device__ float g_H1[N * F];       // layer-1 activation
__device__ int   g_cnt[N];          // in-degree per dst (col-sums of A)
__device__ int   g_csr[N * CSRW];   // fixed-slot CSR: row i at [i*CSRW, i*CSRW+cnt[i])

// ---------------- f32x2 packed helpers ------------------------------------
__device__ __forceinline__ uint64_t pk2(float lo, float hi) {
    uint64_t r;
    asm("mov.b64 %0, {%1, %2};" : "=l"(r) : "f"(lo), "f"(hi));
    return r;
}
__device__ __forceinline__ uint64_t fma2(uint64_t a, uint64_t b, uint64_t c) {
    uint64_t d;
    asm("fma.rn.f32x2 %0, %1, %2, %3;" : "=l"(d) : "l"(a), "l"(b), "l"(c));
    return d;
}
__device__ __forceinline__ void upk2(uint64_t v, float& lo, float& hi) {
    asm("mov.b64 {%0, %1}, %2;" : "=f"(lo), "=f"(hi) : "l"(v));
}

// ---------------- gemm body: out[r,:] = M[r,:] @ W (unscaled) --------------
// 256 threads, 16 rows x 128 cols per block. Thread: 2 rows (f32x2) x 4 cols.
__device__ __forceinline__ void gemm_body(const float* __restrict__ M,
                                          const float* __restrict__ W,
                                          float* __restrict__ out,
                                          int rowBase, int tid,
                                          float* Xs /* 128*XS_STRIDE */) {
    // Fill Xs transposed: Xs[k*XS_STRIDE + r] = M[rowBase+r][k]
    #pragma unroll
    for (int it = 0; it < 8; it++) {
        int idx = tid + 256 * it;        // 2048 elements
        int r = idx >> 7;
        int k = idx & 127;
        Xs[k * XS_STRIDE + r] = M[(rowBase + r) * F + k];
    }
    __syncthreads();

    const float4* W4 = (const float4*)W;
    int cg = tid & 31;           // cols [4cg, 4cg+4)
    int rp = tid >> 5;           // 0..7 -> rows 2rp, 2rp+1

    uint64_t acc[4];
    #pragma unroll
    for (int c = 0; c < 4; c++) acc[c] = 0;

    float4 w = W4[cg];           // prefetch k=0
    #pragma unroll 8
    for (int k = 0; k < 128; k++) {
        float4 wc = w;
        if (k < 127) w = W4[(k + 1) * 32 + cg];
        uint64_t xp = *(const uint64_t*)&Xs[k * XS_STRIDE + 2 * rp];  // rows 2rp,2rp+1 (warp-broadcast)
        acc[0] = fma2(xp, pk2(wc.x, wc.x), acc[0]);
        acc[1] = fma2(xp, pk2(wc.y, wc.y), acc[1]);
        acc[2] = fma2(xp, pk2(wc.z, wc.z), acc[2]);
        acc[3] = fma2(xp, pk2(wc.w, wc.w), acc[3]);
    }

    float lo[4], hi[4];
    #pragma unroll
    for (int c = 0; c < 4; c++) upk2(acc[c], lo[c], hi[c]);
    float4* out4 = (float4*)out;
    int rowA = rowBase + 2 * rp;
    out4[rowA * 32 + cg]       = make_float4(lo[0], lo[1], lo[2], lo[3]);
    out4[(rowA + 1) * 32 + cg] = make_float4(hi[0], hi[1], hi[2], hi[3]);
}

// ---------------- extract body (one pass over A slice) ---------------------
__device__ __forceinline__ void extract_body(const float* __restrict__ A,
                                             int bid, int tid) {
    const float4* A4 = (const float4*)A;
    int base = bid * 2048;   // float4 units per block: 256*8
    #pragma unroll
    for (int s = 0; s < 8; s++) {
        int q = base + tid + 256 * s;
        float4 v = A4[q];
        int idx0 = q * 4;
        float vv[4] = {v.x, v.y, v.z, v.w};
        #pragma unroll
        for (int c = 0; c < 4; c++) {
            if (vv[c] != 0.0f) {
                int idx = idx0 + c;
                int i = idx & (N - 1);   // col = dst
                int j = idx >> 13;       // row = src
                int p = atomicAdd(&g_cnt[i], 1);
                if (p < CSRW) g_csr[i * CSRW + p] = j;
            }
        }
    }
}

// ---------------- fused: extract (blocks 0..8191) + gemm1 (512 more) -------
__global__ void __launch_bounds__(256)
fused_extract_gemm_kernel(const float* __restrict__ A,
                          const float* __restrict__ X,
                          const float* __restrict__ W1,
                          float* __restrict__ Z) {
    __shared__ float Xs[128 * XS_STRIDE];
    int b = blockIdx.x;
    if (b < 8192) {
        extract_body(A, b, threadIdx.x);
    } else {
        gemm_body(X, W1, Z, (b - 8192) * GEMM_ROWS, threadIdx.x, Xs);
    }
}

// ---------------- standalone gemm (layer 2) --------------------------------
__global__ void __launch_bounds__(256)
gemm_kernel(const float* __restrict__ M, const float* __restrict__ W,
            float* __restrict__ out) {
    __shared__ float Xs[128 * XS_STRIDE];
    gemm_body(M, W, out, blockIdx.x * GEMM_ROWS, threadIdx.x, Xs);
}

// ---- SpMM: out[i,:] = relu(dis_i*(dis_i*Z[i,:] + sum dis_j*Z[j,:]) + b) ----
__global__ void spmm_kernel(const float* __restrict__ Z,
                            const float* __restrict__ bias,
                            float* __restrict__ out) {
    __shared__ int   sidx[CSRW];
    __shared__ float sdis[CSRW];
    int i = blockIdx.x;
    int f = threadIdx.x;  // 128
    int cnt = g_cnt[i];
    int m = cnt < CSRW ? cnt : CSRW;

    if (f < m) {
        int s = g_csr[i * CSRW + f];
        sidx[f] = s;
        sdis[f] = rsqrtf((float)g_cnt[s] + 1.0f);
    }
    __syncthreads();

    float dis_i = rsqrtf((float)cnt + 1.0f);
    float acc = dis_i * Z[i * F + f];  // self-loop (I term)

    int e = 0;
    for (; e + 8 <= m; e += 8) {
        float a0 = sdis[e]     * Z[sidx[e]     * F + f];
        float a1 = sdis[e + 1] * Z[sidx[e + 1] * F + f];
        float a2 = sdis[e + 2] * Z[sidx[e + 2] * F + f];
        float a3 = sdis[e + 3] * Z[sidx[e + 3] * F + f];
        float a4 = sdis[e + 4] * Z[sidx[e + 4] * F + f];
        float a5 = sdis[e + 5] * Z[sidx[e + 5] * F + f];
        float a6 = sdis[e + 6] * Z[sidx[e + 6] * F + f];
        float a7 = sdis[e + 7] * Z[sidx[e + 7] * F + f];
        acc += ((a0 + a1) + (a2 + a3)) + ((a4 + a5) + (a6 + a7));
    }
    for (; e < m; e++) acc += sdis[e] * Z[sidx[e] * F + f];

    float r = dis_i * acc + bias[f];
    out[i * F + f] = fmaxf(r, 0.0f);
}

// ---------------- launch ---------------------------------------------------
extern "C" void kernel_launch(void* const* d_in, const int* in_sizes, int n_in,
                              void* d_out, int out_size) {
    const float* X  = (const float*)d_in[0];
    const float* A  = (const float*)d_in[1];
    const float* W1 = (const float*)d_in[2];
    const float* b1 = (const float*)d_in[3];
    const float* W2 = (const float*)d_in[4];
    const float* b2 = (const float*)d_in[5];
    float* out = (float*)d_out;

    float* Z;   cudaGetSymbolAddress((void**)&Z,   g_Z);
    float* H1;  cudaGetSymbolAddress((void**)&H1,  g_H1);
    int*   cnt; cudaGetSymbolAddress((void**)&cnt, g_cnt);

    cudaMemsetAsync(cnt, 0, N * sizeof(int));

    // extract CSR (blocks 0..8191) + layer-1 GEMM (blocks 8192..8703), overlapped
    fused_extract_gemm_kernel<<<8192 + GEMM_GRID, 256>>>(A, X, W1, Z);

    spmm_kernel<<<8192, 128>>>(Z, b1, H1);    // H1 = relu(An@(X@W1) + b1)
    gemm_kernel<<<GEMM_GRID, 256>>>(H1, W2, Z);
    spmm_kernel<<<8192, 128>>>(Z, b2, out);   // out = relu(An@(H1@W2) + b2)
}

// round 5
// speedup vs baseline: 1.1091x; 1.0851x over previous
#include <cuda_runtime.h>
#include <cuda_bf16.h>
#include <cstdint>

#define N 8192
#define F 128
#define CSRW 128        // fixed CSR row width; max in-degree ~60 for Binomial(8192, 32/8192)
#define GEMM_ROWS 32    // rows per gemm block
#define GEMM_GRID (N / GEMM_ROWS)   // 256
#define XS_STRIDE 34    // even => 8B-aligned LDS.64 reads; 2-way conflict on fill only

// ---------------- scratch (static device globals; no allocation) ----------
__device__ float g_Z[N * F];        // UNscaled GEMM output (SpMM input)
__device__ float g_H1[N * F];       // layer-1 activation
__device__ int   g_cnt[N];          // in-degree per dst (col-sums of A)
__device__ int   g_csr[N * CSRW];   // fixed-slot CSR: row i at [i*CSRW, i*CSRW+cnt[i])

// ---------------- f32x2 packed helpers ------------------------------------
__device__ __forceinline__ uint64_t pk2(float lo, float hi) {
    uint64_t r;
    asm("mov.b64 %0, {%1, %2};" : "=l"(r) : "f"(lo), "f"(hi));
    return r;
}
__device__ __forceinline__ uint64_t fma2(uint64_t a, uint64_t b, uint64_t c) {
    uint64_t d;
    asm("fma.rn.f32x2 %0, %1, %2, %3;" : "=l"(d) : "l"(a), "l"(b), "l"(c));
    return d;
}
__device__ __forceinline__ void upk2(uint64_t v, float& lo, float& hi) {
    asm("mov.b64 {%0, %1}, %2;" : "=f"(lo), "=f"(hi) : "l"(v));
}

// ---------------- gemm body: out[r,:] = M[r,:] @ W (unscaled) --------------
// 256 threads, 32 rows x 128 cols per block. Thread: 4 rows (2 f32x2 pairs) x 4 cols.
// 8 f32x2 accumulators; W prefetched one k ahead (L1-resident, 64KB).
__device__ __forceinline__ void gemm_body(const float* __restrict__ M,
                                          const float* __restrict__ W,
                                          float* __restrict__ out,
                                          int rowBase, int tid,
                                          float* Xs /* 128*XS_STRIDE */) {
    // Fill Xs transposed: Xs[k*XS_STRIDE + r] = M[rowBase+r][k]; coalesced reads.
    #pragma unroll
    for (int it = 0; it < 16; it++) {
        int idx = tid + 256 * it;        // 4096 elements
        int r = idx >> 7;                // 0..31
        int k = idx & 127;
        Xs[k * XS_STRIDE + r] = M[(rowBase + r) * F + k];
    }
    __syncthreads();

    const float4* W4 = (const float4*)W;
    int cg = tid & 31;           // cols [4cg, 4cg+4)
    int rg = tid >> 5;           // 0..7 -> rows [4rg, 4rg+4)

    uint64_t acc[2][4];          // [row pair][col]
    #pragma unroll
    for (int p = 0; p < 2; p++)
        #pragma unroll
        for (int c = 0; c < 4; c++) acc[p][c] = 0;

    float4 w = W4[cg];           // prefetch k=0
    #pragma unroll 8
    for (int k = 0; k < 128; k++) {
        float4 wc = w;
        if (k < 127) w = W4[(k + 1) * 32 + cg];
        const float* xrow = &Xs[k * XS_STRIDE + 4 * rg];
        uint64_t xp0 = *(const uint64_t*)(xrow);       // rows 4rg, 4rg+1 (broadcast)
        uint64_t xp1 = *(const uint64_t*)(xrow + 2);   // rows 4rg+2, 4rg+3
        uint64_t wd0 = pk2(wc.x, wc.x);
        uint64_t wd1 = pk2(wc.y, wc.y);
        uint64_t wd2 = pk2(wc.z, wc.z);
        uint64_t wd3 = pk2(wc.w, wc.w);
        acc[0][0] = fma2(xp0, wd0, acc[0][0]);
        acc[0][1] = fma2(xp0, wd1, acc[0][1]);
        acc[0][2] = fma2(xp0, wd2, acc[0][2]);
        acc[0][3] = fma2(xp0, wd3, acc[0][3]);
        acc[1][0] = fma2(xp1, wd0, acc[1][0]);
        acc[1][1] = fma2(xp1, wd1, acc[1][1]);
        acc[1][2] = fma2(xp1, wd2, acc[1][2]);
        acc[1][3] = fma2(xp1, wd3, acc[1][3]);
    }

    float4* out4 = (float4*)out;
    #pragma unroll
    for (int p = 0; p < 2; p++) {
        float lo[4], hi[4];
        #pragma unroll
        for (int c = 0; c < 4; c++) upk2(acc[p][c], lo[c], hi[c]);
        int rowA = rowBase + 4 * rg + 2 * p;
        out4[rowA * 32 + cg]       = make_float4(lo[0], lo[1], lo[2], lo[3]);
        out4[(rowA + 1) * 32 + cg] = make_float4(hi[0], hi[1], hi[2], hi[3]);
    }
}

// ---------------- extract body (one pass over A slice) ---------------------
__device__ __forceinline__ void extract_body(const float* __restrict__ A,
                                             int bid, int tid) {
    const float4* A4 = (const float4*)A;
    int base = bid * 2048;   // float4 units per block: 256*8
    #pragma unroll
    for (int s = 0; s < 8; s++) {
        int q = base + tid + 256 * s;
        float4 v = A4[q];
        int idx0 = q * 4;
        float vv[4] = {v.x, v.y, v.z, v.w};
        #pragma unroll
        for (int c = 0; c < 4; c++) {
            if (vv[c] != 0.0f) {
                int idx = idx0 + c;
                int i = idx & (N - 1);   // col = dst
                int j = idx >> 13;       // row = src
                int p = atomicAdd(&g_cnt[i], 1);
                if (p < CSRW) g_csr[i * CSRW + p] = j;
            }
        }
    }
}

// ------- fused: gemm1 (blocks 0..255, dispatched FIRST) + extract ----------
__global__ void __launch_bounds__(256)
fused_extract_gemm_kernel(const float* __restrict__ A,
                          const float* __restrict__ X,
                          const float* __restrict__ W1,
                          float* __restrict__ Z) {
    __shared__ float Xs[128 * XS_STRIDE];
    int b = blockIdx.x;
    if (b < GEMM_GRID) {
        gemm_body(X, W1, Z, b * GEMM_ROWS, threadIdx.x, Xs);
    } else {
        extract_body(A, b - GEMM_GRID, threadIdx.x);
    }
}

// ---------------- standalone gemm (layer 2) --------------------------------
__global__ void __launch_bounds__(256)
gemm_kernel(const float* __restrict__ M, const float* __restrict__ W,
            float* __restrict__ out) {
    __shared__ float Xs[128 * XS_STRIDE];
    gemm_body(M, W, out, blockIdx.x * GEMM_ROWS, threadIdx.x, Xs);
}

// ---- SpMM: out[i,:] = relu(dis_i*(dis_i*Z[i,:] + sum dis_j*Z[j,:]) + b) ----
__global__ void spmm_kernel(const float* __restrict__ Z,
                            const float* __restrict__ bias,
                            float* __restrict__ out) {
    __shared__ int   sidx[CSRW];
    __shared__ float sdis[CSRW];
    int i = blockIdx.x;
    int f = threadIdx.x;  // 128
    int cnt = g_cnt[i];
    int m = cnt < CSRW ? cnt : CSRW;

    if (f < m) {
        int s = g_csr[i * CSRW + f];
        sidx[f] = s;
        sdis[f] = rsqrtf((float)g_cnt[s] + 1.0f);
    }
    __syncthreads();

    float dis_i = rsqrtf((float)cnt + 1.0f);
    float acc = dis_i * Z[i * F + f];  // self-loop (I term)

    int e = 0;
    for (; e + 8 <= m; e += 8) {
        float a0 = sdis[e]     * Z[sidx[e]     * F + f];
        float a1 = sdis[e + 1] * Z[sidx[e + 1] * F + f];
        float a2 = sdis[e + 2] * Z[sidx[e + 2] * F + f];
        float a3 = sdis[e + 3] * Z[sidx[e + 3] * F + f];
        float a4 = sdis[e + 4] * Z[sidx[e + 4] * F + f];
        float a5 = sdis[e + 5] * Z[sidx[e + 5] * F + f];
        float a6 = sdis[e + 6] * Z[sidx[e + 6] * F + f];
        float a7 = sdis[e + 7] * Z[sidx[e + 7] * F + f];
        acc += ((a0 + a1) + (a2 + a3)) + ((a4 + a5) + (a6 + a7));
    }
    for (; e < m; e++) acc += sdis[e] * Z[sidx[e] * F + f];

    float r = dis_i * acc + bias[f];
    out[i * F + f] = fmaxf(r, 0.0f);
}

// ---------------- launch ---------------------------------------------------
extern "C" void kernel_launch(void* const* d_in, const int* in_sizes, int n_in,
                              void* d_out, int out_size) {
    const float* X  = (const float*)d_in[0];
    const float* A  = (const float*)d_in[1];
    const float* W1 = (const float*)d_in[2];
    const float* b1 = (const float*)d_in[3];
    const float* W2 = (const float*)d_in[4];
    const float* b2 = (const float*)d_in[5];
    float* out = (float*)d_out;

    float* Z;   cudaGetSymbolAddress((void**)&Z,   g_Z);
    float* H1;  cudaGetSymbolAddress((void**)&H1,  g_H1);
    int*   cnt; cudaGetSymbolAddress((void**)&cnt, g_cnt);

    cudaMemsetAsync(cnt, 0, N * sizeof(int));

    // gemm1 (blocks 0..255, start immediately) + extract CSR (blocks 256..8447)
    fused_extract_gemm_kernel<<<GEMM_GRID + 8192, 256>>>(A, X, W1, Z);

    spmm_kernel<<<8192, 128>>>(Z, b1, H1);    // H1 = relu(An@(X@W1) + b1)
    gemm_kernel<<<GEMM_GRID, 256>>>(H1, W2, Z);
    spmm_kernel<<<8192, 128>>>(Z, b2, out);   // out = relu(An@(H1@W2) + b2)
}

// round 6
// speedup vs baseline: 1.1716x; 1.0564x over previous
#include <cuda_runtime.h>
#include <cuda_bf16.h>
#include <cstdint>

#define N 8192
#define F 128
#define CSRW 128        // fixed CSR row width; max in-degree ~60 for Binomial(8192, 32/8192)
#define GEMM_ROWS 32    // rows per gemm block
#define GEMM_GRID (N / GEMM_ROWS)   // 256
#define XS_STRIDE 34    // even => 8B-aligned LDS.64 reads; 2-way conflict on fill only

// ---------------- scratch (static device globals; no allocation) ----------
__device__ float g_Z[N * F];        // UNscaled GEMM output (SpMM input)
__device__ float g_H1[N * F];       // layer-1 activation
__device__ int   g_cnt[N];          // in-degree per dst (col-sums of A)
__device__ int   g_csr[N * CSRW];   // fixed-slot CSR: row i at [i*CSRW, i*CSRW+cnt[i])

// ---------------- f32x2 packed helpers ------------------------------------
__device__ __forceinline__ uint64_t pk2(float lo, float hi) {
    uint64_t r;
    asm("mov.b64 %0, {%1, %2};" : "=l"(r) : "f"(lo), "f"(hi));
    return r;
}
__device__ __forceinline__ uint64_t fma2(uint64_t a, uint64_t b, uint64_t c) {
    uint64_t d;
    asm("fma.rn.f32x2 %0, %1, %2, %3;" : "=l"(d) : "l"(a), "l"(b), "l"(c));
    return d;
}
__device__ __forceinline__ void upk2(uint64_t v, float& lo, float& hi) {
    asm("mov.b64 {%0, %1}, %2;" : "=f"(lo), "=f"(hi) : "l"(v));
}

// ---------------- gemm body: out[r,:] = M[r,:] @ W (unscaled) --------------
// 256 threads, 32 rows x 128 cols per block. Thread: 4 rows (2 f32x2 pairs) x 4 cols.
__device__ __forceinline__ void gemm_body(const float* __restrict__ M,
                                          const float* __restrict__ W,
                                          float* __restrict__ out,
                                          int rowBase, int tid,
                                          float* Xs /* 128*XS_STRIDE */) {
    #pragma unroll
    for (int it = 0; it < 16; it++) {
        int idx = tid + 256 * it;        // 4096 elements
        int r = idx >> 7;                // 0..31
        int k = idx & 127;
        Xs[k * XS_STRIDE + r] = M[(rowBase + r) * F + k];
    }
    __syncthreads();

    const float4* W4 = (const float4*)W;
    int cg = tid & 31;           // cols [4cg, 4cg+4)
    int rg = tid >> 5;           // 0..7 -> rows [4rg, 4rg+4)

    uint64_t acc[2][4];
    #pragma unroll
    for (int p = 0; p < 2; p++)
        #pragma unroll
        for (int c = 0; c < 4; c++) acc[p][c] = 0;

    float4 w = W4[cg];           // prefetch k=0
    #pragma unroll 8
    for (int k = 0; k < 128; k++) {
        float4 wc = w;
        if (k < 127) w = W4[(k + 1) * 32 + cg];
        const float* xrow = &Xs[k * XS_STRIDE + 4 * rg];
        uint64_t xp0 = *(const uint64_t*)(xrow);
        uint64_t xp1 = *(const uint64_t*)(xrow + 2);
        uint64_t wd0 = pk2(wc.x, wc.x);
        uint64_t wd1 = pk2(wc.y, wc.y);
        uint64_t wd2 = pk2(wc.z, wc.z);
        uint64_t wd3 = pk2(wc.w, wc.w);
        acc[0][0] = fma2(xp0, wd0, acc[0][0]);
        acc[0][1] = fma2(xp0, wd1, acc[0][1]);
        acc[0][2] = fma2(xp0, wd2, acc[0][2]);
        acc[0][3] = fma2(xp0, wd3, acc[0][3]);
        acc[1][0] = fma2(xp1, wd0, acc[1][0]);
        acc[1][1] = fma2(xp1, wd1, acc[1][1]);
        acc[1][2] = fma2(xp1, wd2, acc[1][2]);
        acc[1][3] = fma2(xp1, wd3, acc[1][3]);
    }

    float4* out4 = (float4*)out;
    #pragma unroll
    for (int p = 0; p < 2; p++) {
        float lo[4], hi[4];
        #pragma unroll
        for (int c = 0; c < 4; c++) upk2(acc[p][c], lo[c], hi[c]);
        int rowA = rowBase + 4 * rg + 2 * p;
        out4[rowA * 32 + cg]       = make_float4(lo[0], lo[1], lo[2], lo[3]);
        out4[(rowA + 1) * 32 + cg] = make_float4(hi[0], hi[1], hi[2], hi[3]);
    }
}

// ---------------- extract body (one pass over A slice) ---------------------
__device__ __forceinline__ void extract_body(const float* __restrict__ A,
                                             int bid, int tid) {
    const float4* A4 = (const float4*)A;
    int base = bid * 2048;
    #pragma unroll
    for (int s = 0; s < 8; s++) {
        int q = base + tid + 256 * s;
        float4 v = A4[q];
        int idx0 = q * 4;
        float vv[4] = {v.x, v.y, v.z, v.w};
        #pragma unroll
        for (int c = 0; c < 4; c++) {
            if (vv[c] != 0.0f) {
                int idx = idx0 + c;
                int i = idx & (N - 1);   // col = dst
                int j = idx >> 13;       // row = src
                int p = atomicAdd(&g_cnt[i], 1);
                if (p < CSRW) g_csr[i * CSRW + p] = j;
            }
        }
    }
}

// ------- fused: gemm1 (blocks 0..255, dispatched FIRST) + extract ----------
__global__ void __launch_bounds__(256)
fused_extract_gemm_kernel(const float* __restrict__ A,
                          const float* __restrict__ X,
                          const float* __restrict__ W1,
                          float* __restrict__ Z) {
    __shared__ float Xs[128 * XS_STRIDE];
    int b = blockIdx.x;
    if (b < GEMM_GRID) {
        gemm_body(X, W1, Z, b * GEMM_ROWS, threadIdx.x, Xs);
    } else {
        extract_body(A, b - GEMM_GRID, threadIdx.x);
    }
}

// ---------------- standalone gemm (layer 2) --------------------------------
__global__ void __launch_bounds__(256)
gemm_kernel(const float* __restrict__ M, const float* __restrict__ W,
            float* __restrict__ out) {
    __shared__ float Xs[128 * XS_STRIDE];
    gemm_body(M, W, out, blockIdx.x * GEMM_ROWS, threadIdx.x, Xs);
}

// ---- SpMM float4: one warp per dst row; lane owns 4 features --------------
// out[i,:] = relu(dis_i*(dis_i*Z[i,:] + sum_j dis_j*Z[j,:]) + b)
__global__ void __launch_bounds__(256)
spmm_kernel(const float* __restrict__ Z,
            const float* __restrict__ bias,
            float* __restrict__ out) {
    __shared__ int   sidx[8][CSRW];   // float4-row offsets (src*32)
    __shared__ float sdis[8][CSRW];
    int warp = threadIdx.x >> 5;
    int lane = threadIdx.x & 31;
    int i = blockIdx.x * 8 + warp;

    int cnt = g_cnt[i];
    int m = cnt < CSRW ? cnt : CSRW;

    // warp-private staging: indices as float4-row offsets, plus per-src dis
    for (int e = lane; e < m; e += 32) {
        int s = g_csr[i * CSRW + e];
        sidx[warp][e] = s * 32;
        sdis[warp][e] = rsqrtf((float)g_cnt[s] + 1.0f);
    }
    __syncwarp();

    const float4* Z4 = (const float4*)Z;
    float dis_i = rsqrtf((float)cnt + 1.0f);

    float4 self = Z4[i * 32 + lane];
    uint64_t di = pk2(dis_i, dis_i);
    uint64_t acc0 = fma2(*(const uint64_t*)&self.x, di, 0ull);
    uint64_t acc1 = fma2(*(const uint64_t*)&self.z, di, 0ull);

    int e = 0;
    for (; e + 4 <= m; e += 4) {
        float4 v0 = Z4[sidx[warp][e]     + lane];
        float4 v1 = Z4[sidx[warp][e + 1] + lane];
        float4 v2 = Z4[sidx[warp][e + 2] + lane];
        float4 v3 = Z4[sidx[warp][e + 3] + lane];
        uint64_t d0 = pk2(sdis[warp][e],     sdis[warp][e]);
        uint64_t d1 = pk2(sdis[warp][e + 1], sdis[warp][e + 1]);
        uint64_t d2 = pk2(sdis[warp][e + 2], sdis[warp][e + 2]);
        uint64_t d3 = pk2(sdis[warp][e + 3], sdis[warp][e + 3]);
        acc0 = fma2(*(const uint64_t*)&v0.x, d0, acc0);
        acc1 = fma2(*(const uint64_t*)&v0.z, d0, acc1);
        acc0 = fma2(*(const uint64_t*)&v1.x, d1, acc0);
        acc1 = fma2(*(const uint64_t*)&v1.z, d1, acc1);
        acc0 = fma2(*(const uint64_t*)&v2.x, d2, acc0);
        acc1 = fma2(*(const uint64_t*)&v2.z, d2, acc1);
        acc0 = fma2(*(const uint64_t*)&v3.x, d3, acc0);
        acc1 = fma2(*(const uint64_t*)&v3.z, d3, acc1);
    }
    for (; e < m; e++) {
        float4 v = Z4[sidx[warp][e] + lane];
        uint64_t d = pk2(sdis[warp][e], sdis[warp][e]);
        acc0 = fma2(*(const uint64_t*)&v.x, d, acc0);
        acc1 = fma2(*(const uint64_t*)&v.z, d, acc1);
    }

    float a0, a1, a2, a3;
    upk2(acc0, a0, a1);
    upk2(acc1, a2, a3);
    float4 b4 = ((const float4*)bias)[lane];
    float4 r;
    r.x = fmaxf(dis_i * a0 + b4.x, 0.0f);
    r.y = fmaxf(dis_i * a1 + b4.y, 0.0f);
    r.z = fmaxf(dis_i * a2 + b4.z, 0.0f);
    r.w = fmaxf(dis_i * a3 + b4.w, 0.0f);
    ((float4*)out)[i * 32 + lane] = r;
}

// ---------------- launch ---------------------------------------------------
extern "C" void kernel_launch(void* const* d_in, const int* in_sizes, int n_in,
                              void* d_out, int out_size) {
    const float* X  = (const float*)d_in[0];
    const float* A  = (const float*)d_in[1];
    const float* W1 = (const float*)d_in[2];
    const float* b1 = (const float*)d_in[3];
    const float* W2 = (const float*)d_in[4];
    const float* b2 = (const float*)d_in[5];
    float* out = (float*)d_out;

    float* Z;   cudaGetSymbolAddress((void**)&Z,   g_Z);
    float* H1;  cudaGetSymbolAddress((void**)&H1,  g_H1);
    int*   cnt; cudaGetSymbolAddress((void**)&cnt, g_cnt);

    cudaMemsetAsync(cnt, 0, N * sizeof(int));

    // gemm1 (blocks 0..255, start immediately) + extract CSR (blocks 256..8447)
    fused_extract_gemm_kernel<<<GEMM_GRID + 8192, 256>>>(A, X, W1, Z);

    spmm_kernel<<<1024, 256>>>(Z, b1, H1);    // H1 = relu(An@(X@W1) + b1)
    gemm_kernel<<<GEMM_GRID, 256>>>(H1, W2, Z);
    spmm_kernel<<<1024, 256>>>(Z, b2, out);   // out = relu(An@(H1@W2) + b2)
}

// round 7
// speedup vs baseline: 1.2002x; 1.0244x over previous
#include <cuda_runtime.h>
#include <cuda_bf16.h>
#include <cuda_fp16.h>
#include <cstdint>

#define N 8192
#define F 128
#define CSRW 128        // fixed CSR row width; max in-degree ~60 for Binomial(8192, 32/8192)
#define GEMM_ROWS 32    // rows per gemm block
#define GEMM_GRID (N / GEMM_ROWS)   // 256
#define XS_STRIDE 34    // even => 8B-aligned LDS.64 reads; 2-way conflict on fill only

// ---------------- scratch (static device globals; no allocation) ----------
__device__ __half g_Z[N * F];       // UNscaled GEMM output, fp16 (SpMM gather input)
__device__ float  g_H1[N * F];      // layer-1 activation (fp32, gemm2 input)
__device__ int    g_cnt[N];         // in-degree per dst (col-sums of A)
__device__ int    g_csr[N * CSRW];  // fixed-slot CSR: row i at [i*CSRW, i*CSRW+cnt[i])

// ---------------- f32x2 packed helpers ------------------------------------
__device__ __forceinline__ uint64_t pk2(float lo, float hi) {
    uint64_t r;
    asm("mov.b64 %0, {%1, %2};" : "=l"(r) : "f"(lo), "f"(hi));
    return r;
}
__device__ __forceinline__ uint64_t fma2(uint64_t a, uint64_t b, uint64_t c) {
    uint64_t d;
    asm("fma.rn.f32x2 %0, %1, %2, %3;" : "=l"(d) : "l"(a), "l"(b), "l"(c));
    return d;
}
__device__ __forceinline__ void upk2(uint64_t v, float& lo, float& hi) {
    asm("mov.b64 {%0, %1}, %2;" : "=f"(lo), "=f"(hi) : "l"(v));
}

// -------- gemm body: out[r,:] = half(M[r,:] @ W)  (unscaled, fp16 out) -----
// 256 threads, 32 rows x 128 cols per block. Thread: 4 rows (2 f32x2 pairs) x 4 cols.
__device__ __forceinline__ void gemm_body_h(const float* __restrict__ M,
                                            const float* __restrict__ W,
                                            __half* __restrict__ out,
                                            int rowBase, int tid,
                                            float* Xs /* 128*XS_STRIDE */) {
    #pragma unroll
    for (int it = 0; it < 16; it++) {
        int idx = tid + 256 * it;        // 4096 elements
        int r = idx >> 7;                // 0..31
        int k = idx & 127;
        Xs[k * XS_STRIDE + r] = M[(rowBase + r) * F + k];
    }
    __syncthreads();

    const float4* W4 = (const float4*)W;
    int cg = tid & 31;           // cols [4cg, 4cg+4)
    int rg = tid >> 5;           // 0..7 -> rows [4rg, 4rg+4)

    uint64_t acc[2][4];
    #pragma unroll
    for (int p = 0; p < 2; p++)
        #pragma unroll
        for (int c = 0; c < 4; c++) acc[p][c] = 0;

    float4 w = W4[cg];           // prefetch k=0
    #pragma unroll 8
    for (int k = 0; k < 128; k++) {
        float4 wc = w;
        if (k < 127) w = W4[(k + 1) * 32 + cg];
        const float* xrow = &Xs[k * XS_STRIDE + 4 * rg];
        uint64_t xp0 = *(const uint64_t*)(xrow);
        uint64_t xp1 = *(const uint64_t*)(xrow + 2);
        uint64_t wd0 = pk2(wc.x, wc.x);
        uint64_t wd1 = pk2(wc.y, wc.y);
        uint64_t wd2 = pk2(wc.z, wc.z);
        uint64_t wd3 = pk2(wc.w, wc.w);
        acc[0][0] = fma2(xp0, wd0, acc[0][0]);
        acc[0][1] = fma2(xp0, wd1, acc[0][1]);
        acc[0][2] = fma2(xp0, wd2, acc[0][2]);
        acc[0][3] = fma2(xp0, wd3, acc[0][3]);
        acc[1][0] = fma2(xp1, wd0, acc[1][0]);
        acc[1][1] = fma2(xp1, wd1, acc[1][1]);
        acc[1][2] = fma2(xp1, wd2, acc[1][2]);
        acc[1][3] = fma2(xp1, wd3, acc[1][3]);
    }

    uint2* out2 = (uint2*)out;   // 4 halves per uint2; 32 uint2 per row
    #pragma unroll
    for (int p = 0; p < 2; p++) {
        float lo[4], hi[4];
        #pragma unroll
        for (int c = 0; c < 4; c++) upk2(acc[p][c], lo[c], hi[c]);
        int rowA = rowBase + 4 * rg + 2 * p;
        __half2 a01 = __floats2half2_rn(lo[0], lo[1]);
        __half2 a23 = __floats2half2_rn(lo[2], lo[3]);
        __half2 b01 = __floats2half2_rn(hi[0], hi[1]);
        __half2 b23 = __floats2half2_rn(hi[2], hi[3]);
        uint2 va, vb;
        va.x = *(uint32_t*)&a01; va.y = *(uint32_t*)&a23;
        vb.x = *(uint32_t*)&b01; vb.y = *(uint32_t*)&b23;
        out2[rowA * 32 + cg]       = va;
        out2[(rowA + 1) * 32 + cg] = vb;
    }
}

// ---------------- extract body (one pass over A slice) ---------------------
__device__ __forceinline__ void extract_body(const float* __restrict__ A,
                                             int bid, int tid) {
    const float4* A4 = (const float4*)A;
    int base = bid * 2048;
    #pragma unroll
    for (int s = 0; s < 8; s++) {
        int q = base + tid + 256 * s;
        float4 v = A4[q];
        int idx0 = q * 4;
        float vv[4] = {v.x, v.y, v.z, v.w};
        #pragma unroll
        for (int c = 0; c < 4; c++) {
            if (vv[c] != 0.0f) {
                int idx = idx0 + c;
                int i = idx & (N - 1);   // col = dst
                int j = idx >> 13;       // row = src
                int p = atomicAdd(&g_cnt[i], 1);
                if (p < CSRW) g_csr[i * CSRW + p] = j;
            }
        }
    }
}

// ------- fused: gemm1 (blocks 0..255, dispatched FIRST) + extract ----------
__global__ void __launch_bounds__(256)
fused_extract_gemm_kernel(const float* __restrict__ A,
                          const float* __restrict__ X,
                          const float* __restrict__ W1,
                          __half* __restrict__ Z) {
    __shared__ float Xs[128 * XS_STRIDE];
    int b = blockIdx.x;
    if (b < GEMM_GRID) {
        gemm_body_h(X, W1, Z, b * GEMM_ROWS, threadIdx.x, Xs);
    } else {
        extract_body(A, b - GEMM_GRID, threadIdx.x);
    }
}

// ---------------- standalone gemm (layer 2) --------------------------------
__global__ void __launch_bounds__(256)
gemm_kernel(const float* __restrict__ M, const float* __restrict__ W,
            __half* __restrict__ out) {
    __shared__ float Xs[128 * XS_STRIDE];
    gemm_body_h(M, W, out, blockIdx.x * GEMM_ROWS, threadIdx.x, Xs);
}

// ---- SpMM fp16-gather: one warp per dst row; lane owns 4 features ---------
// out[i,:] = relu(dis_i*(dis_i*Z[i,:] + sum_j dis_j*Z[j,:]) + b), fp32 accumulate
__global__ void __launch_bounds__(256)
spmm_kernel(const __half* __restrict__ Z,
            const float* __restrict__ bias,
            float* __restrict__ out) {
    __shared__ int   sidx[8][CSRW];   // uint2-row offsets (src*32)
    __shared__ float sdis[8][CSRW];
    int warp = threadIdx.x >> 5;
    int lane = threadIdx.x & 31;
    int i = blockIdx.x * 8 + warp;

    int cnt = g_cnt[i];
    int m = cnt < CSRW ? cnt : CSRW;

    for (int e = lane; e < m; e += 32) {
        int s = g_csr[i * CSRW + e];
        sidx[warp][e] = s * 32;
        sdis[warp][e] = rsqrtf((float)g_cnt[s] + 1.0f);
    }
    __syncwarp();

    const uint2* Z2 = (const uint2*)Z;   // 4 halves per element
    float dis_i = rsqrtf((float)cnt + 1.0f);
    uint64_t di = pk2(dis_i, dis_i);

    uint2 self = Z2[i * 32 + lane];
    float2 sa = __half22float2(*(const __half2*)&self.x);
    float2 sb = __half22float2(*(const __half2*)&self.y);
    uint64_t acc0 = fma2(pk2(sa.x, sa.y), di, 0ull);
    uint64_t acc1 = fma2(pk2(sb.x, sb.y), di, 0ull);

    int e = 0;
    for (; e + 8 <= m; e += 8) {
        uint2 u[8];
        #pragma unroll
        for (int q = 0; q < 8; q++) u[q] = Z2[sidx[warp][e + q] + lane];
        #pragma unroll
        for (int q = 0; q < 8; q++) {
            float d = sdis[warp][e + q];
            uint64_t dd = pk2(d, d);
            float2 fa = __half22float2(*(const __half2*)&u[q].x);
            float2 fb = __half22float2(*(const __half2*)&u[q].y);
            acc0 = fma2(pk2(fa.x, fa.y), dd, acc0);
            acc1 = fma2(pk2(fb.x, fb.y), dd, acc1);
        }
    }
    for (; e < m; e++) {
        uint2 u = Z2[sidx[warp][e] + lane];
        float d = sdis[warp][e];
        uint64_t dd = pk2(d, d);
        float2 fa = __half22float2(*(const __half2*)&u.x);
        float2 fb = __half22float2(*(const __half2*)&u.y);
        acc0 = fma2(pk2(fa.x, fa.y), dd, acc0);
        acc1 = fma2(pk2(fb.x, fb.y), dd, acc1);
    }

    float a0, a1, a2, a3;
    upk2(acc0, a0, a1);
    upk2(acc1, a2, a3);
    float4 b4 = ((const float4*)bias)[lane];
    float4 r;
    r.x = fmaxf(dis_i * a0 + b4.x, 0.0f);
    r.y = fmaxf(dis_i * a1 + b4.y, 0.0f);
    r.z = fmaxf(dis_i * a2 + b4.z, 0.0f);
    r.w = fmaxf(dis_i * a3 + b4.w, 0.0f);
    ((float4*)out)[i * 32 + lane] = r;
}

// ---------------- launch ---------------------------------------------------
extern "C" void kernel_launch(void* const* d_in, const int* in_sizes, int n_in,
                              void* d_out, int out_size) {
    const float* X  = (const float*)d_in[0];
    const float* A  = (const float*)d_in[1];
    const float* W1 = (const float*)d_in[2];
    const float* b1 = (const float*)d_in[3];
    const float* W2 = (const float*)d_in[4];
    const float* b2 = (const float*)d_in[5];
    float* out = (float*)d_out;

    __half* Z;  cudaGetSymbolAddress((void**)&Z,   g_Z);
    float* H1;  cudaGetSymbolAddress((void**)&H1,  g_H1);
    int*   cnt; cudaGetSymbolAddress((void**)&cnt, g_cnt);

    cudaMemsetAsync(cnt, 0, N * sizeof(int));

    // gemm1 (blocks 0..255, start immediately) + extract CSR (blocks 256..8447)
    fused_extract_gemm_kernel<<<GEMM_GRID + 8192, 256>>>(A, X, W1, Z);

    spmm_kernel<<<1024, 256>>>(Z, b1, H1);    // H1 = relu(An@(X@W1) + b1)
    gemm_kernel<<<GEMM_GRID, 256>>>(H1, W2, Z);
    spmm_kernel<<<1024, 256>>>(Z, b2, out);   // out = relu(An@(H1@W2) + b2)
}

// round 8
// speedup vs baseline: 1.2165x; 1.0136x over previous
#include <cuda_runtime.h>
#include <cuda_bf16.h>
#include <cuda_fp16.h>
#include <cstdint>

#define N 8192
#define F 128
#define CSRW 128        // fixed CSR row width; max in-degree ~60 for Binomial(8192, 32/8192)
#define GEMM_ROWS 16    // rows per gemm block
#define GEMM_GRID (N / GEMM_ROWS)   // 512
#define XS_STRIDE 18    // even => 8B-aligned LDS.64 reads; 2-way conflict on fill only

// ---------------- scratch (static device globals; no allocation) ----------
__device__ __half g_Z[N * F];       // UNscaled GEMM output, fp16 (SpMM gather input)
__device__ float  g_H1[N * F];      // layer-1 activation (fp32, gemm2 input)
__device__ int    g_cnt[N];         // in-degree per dst (col-sums of A)
__device__ int    g_csr[N * CSRW];  // fixed-slot CSR: row i at [i*CSRW, i*CSRW+cnt[i])

// ---------------- f32x2 packed helpers ------------------------------------
__device__ __forceinline__ uint64_t pk2(float lo, float hi) {
    uint64_t r;
    asm("mov.b64 %0, {%1, %2};" : "=l"(r) : "f"(lo), "f"(hi));
    return r;
}
__device__ __forceinline__ uint64_t fma2(uint64_t a, uint64_t b, uint64_t c) {
    uint64_t d;
    asm("fma.rn.f32x2 %0, %1, %2, %3;" : "=l"(d) : "l"(a), "l"(b), "l"(c));
    return d;
}
__device__ __forceinline__ void upk2(uint64_t v, float& lo, float& hi) {
    asm("mov.b64 {%0, %1}, %2;" : "=f"(lo), "=f"(hi) : "l"(v));
}

// -------- gemm body: out[r,:] = half(M[r,:] @ W)  (unscaled, fp16 out) -----
// 256 threads, 16 rows x 128 cols per block (grid 512 => ~28 warps/SM).
// Thread: 2 rows (one f32x2) x 4 cols = 4 fma2 per k. W prefetched one k ahead.
__device__ __forceinline__ void gemm_body_h(const float* __restrict__ M,
                                            const float* __restrict__ W,
                                            __half* __restrict__ out,
                                            int rowBase, int tid,
                                            float* Xs /* 128*XS_STRIDE */) {
    // Fill Xs transposed: Xs[k*XS_STRIDE + r] = M[rowBase+r][k]; coalesced reads.
    #pragma unroll
    for (int it = 0; it < 8; it++) {
        int idx = tid + 256 * it;        // 2048 elements
        int r = idx >> 7;                // 0..15
        int k = idx & 127;
        Xs[k * XS_STRIDE + r] = M[(rowBase + r) * F + k];
    }
    __syncthreads();

    const float4* W4 = (const float4*)W;
    int cg = tid & 31;           // cols [4cg, 4cg+4)
    int rp = tid >> 5;           // 0..7 -> rows 2rp, 2rp+1

    uint64_t acc[4];
    #pragma unroll
    for (int c = 0; c < 4; c++) acc[c] = 0;

    float4 w = W4[cg];           // prefetch k=0
    #pragma unroll 8
    for (int k = 0; k < 128; k++) {
        float4 wc = w;
        if (k < 127) w = W4[(k + 1) * 32 + cg];
        uint64_t xp = *(const uint64_t*)&Xs[k * XS_STRIDE + 2 * rp];  // rows 2rp,2rp+1
        acc[0] = fma2(xp, pk2(wc.x, wc.x), acc[0]);
        acc[1] = fma2(xp, pk2(wc.y, wc.y), acc[1]);
        acc[2] = fma2(xp, pk2(wc.z, wc.z), acc[2]);
        acc[3] = fma2(xp, pk2(wc.w, wc.w), acc[3]);
    }

    float lo[4], hi[4];
    #pragma unroll
    for (int c = 0; c < 4; c++) upk2(acc[c], lo[c], hi[c]);

    uint2* out2 = (uint2*)out;   // 4 halves per uint2; 32 uint2 per row
    int rowA = rowBase + 2 * rp;
    __half2 a01 = __floats2half2_rn(lo[0], lo[1]);
    __half2 a23 = __floats2half2_rn(lo[2], lo[3]);
    __half2 b01 = __floats2half2_rn(hi[0], hi[1]);
    __half2 b23 = __floats2half2_rn(hi[2], hi[3]);
    uint2 va, vb;
    va.x = *(uint32_t*)&a01; va.y = *(uint32_t*)&a23;
    vb.x = *(uint32_t*)&b01; vb.y = *(uint32_t*)&b23;
    out2[rowA * 32 + cg]       = va;
    out2[(rowA + 1) * 32 + cg] = vb;
}

// ---------------- extract body (one pass over A slice) ---------------------
__device__ __forceinline__ void extract_body(const float* __restrict__ A,
                                             int bid, int tid) {
    const float4* A4 = (const float4*)A;
    int base = bid * 2048;
    #pragma unroll
    for (int s = 0; s < 8; s++) {
        int q = base + tid + 256 * s;
        float4 v = A4[q];
        int idx0 = q * 4;
        float vv[4] = {v.x, v.y, v.z, v.w};
        #pragma unroll
        for (int c = 0; c < 4; c++) {
            if (vv[c] != 0.0f) {
                int idx = idx0 + c;
                int i = idx & (N - 1);   // col = dst
                int j = idx >> 13;       // row = src
                int p = atomicAdd(&g_cnt[i], 1);
                if (p < CSRW) g_csr[i * CSRW + p] = j;
            }
        }
    }
}

// ------- fused: gemm1 (blocks 0..511, dispatched FIRST) + extract ----------
__global__ void __launch_bounds__(256)
fused_extract_gemm_kernel(const float* __restrict__ A,
                          const float* __restrict__ X,
                          const float* __restrict__ W1,
                          __half* __restrict__ Z) {
    __shared__ float Xs[128 * XS_STRIDE];
    int b = blockIdx.x;
    if (b < GEMM_GRID) {
        gemm_body_h(X, W1, Z, b * GEMM_ROWS, threadIdx.x, Xs);
    } else {
        extract_body(A, b - GEMM_GRID, threadIdx.x);
    }
}

// ---------------- standalone gemm (layer 2) --------------------------------
__global__ void __launch_bounds__(256)
gemm_kernel(const float* __restrict__ M, const float* __restrict__ W,
            __half* __restrict__ out) {
    __shared__ float Xs[128 * XS_STRIDE];
    gemm_body_h(M, W, out, blockIdx.x * GEMM_ROWS, threadIdx.x, Xs);
}

// ---- SpMM fp16-gather: one warp per dst row; lane owns 4 features ---------
// out[i,:] = relu(dis_i*(dis_i*Z[i,:] + sum_j dis_j*Z[j,:]) + b), fp32 accumulate
__global__ void __launch_bounds__(256)
spmm_kernel(const __half* __restrict__ Z,
            const float* __restrict__ bias,
            float* __restrict__ out) {
    __shared__ int   sidx[8][CSRW];   // uint2-row offsets (src*32)
    __shared__ float sdis[8][CSRW];
    int warp = threadIdx.x >> 5;
    int lane = threadIdx.x & 31;
    int i = blockIdx.x * 8 + warp;

    int cnt = g_cnt[i];
    int m = cnt < CSRW ? cnt : CSRW;

    for (int e = lane; e < m; e += 32) {
        int s = g_csr[i * CSRW + e];
        sidx[warp][e] = s * 32;
        sdis[warp][e] = rsqrtf((float)g_cnt[s] + 1.0f);
    }
    __syncwarp();

    const uint2* Z2 = (const uint2*)Z;   // 4 halves per element
    float dis_i = rsqrtf((float)cnt + 1.0f);
    uint64_t di = pk2(dis_i, dis_i);

    uint2 self = Z2[i * 32 + lane];
    float2 sa = __half22float2(*(const __half2*)&self.x);
    float2 sb = __half22float2(*(const __half2*)&self.y);
    uint64_t acc0 = fma2(pk2(sa.x, sa.y), di, 0ull);
    uint64_t acc1 = fma2(pk2(sb.x, sb.y), di, 0ull);

    int e = 0;
    for (; e + 8 <= m; e += 8) {
        uint2 u[8];
        #pragma unroll
        for (int q = 0; q < 8; q++) u[q] = Z2[sidx[warp][e + q] + lane];
        #pragma unroll
        for (int q = 0; q < 8; q++) {
            float d = sdis[warp][e + q];
            uint64_t dd = pk2(d, d);
            float2 fa = __half22float2(*(const __half2*)&u[q].x);
            float2 fb = __half22float2(*(const __half2*)&u[q].y);
            acc0 = fma2(pk2(fa.x, fa.y), dd, acc0);
            acc1 = fma2(pk2(fb.x, fb.y), dd, acc1);
        }
    }
    for (; e < m; e++) {
        uint2 u = Z2[sidx[warp][e] + lane];
        float d = sdis[warp][e];
        uint64_t dd = pk2(d, d);
        float2 fa = __half22float2(*(const __half2*)&u.x);
        float2 fb = __half22float2(*(const __half2*)&u.y);
        acc0 = fma2(pk2(fa.x, fa.y), dd, acc0);
        acc1 = fma2(pk2(fb.x, fb.y), dd, acc1);
    }

    float a0, a1, a2, a3;
    upk2(acc0, a0, a1);
    upk2(acc1, a2, a3);
    float4 b4 = ((const float4*)bias)[lane];
    float4 r;
    r.x = fmaxf(dis_i * a0 + b4.x, 0.0f);
    r.y = fmaxf(dis_i * a1 + b4.y, 0.0f);
    r.z = fmaxf(dis_i * a2 + b4.z, 0.0f);
    r.w = fmaxf(dis_i * a3 + b4.w, 0.0f);
    ((float4*)out)[i * 32 + lane] = r;
}

// ---------------- launch ---------------------------------------------------
extern "C" void kernel_launch(void* const* d_in, const int* in_sizes, int n_in,
                              void* d_out, int out_size) {
    const float* X  = (const float*)d_in[0];
    const float* A  = (const float*)d_in[1];
    const float* W1 = (const float*)d_in[2];
    const float* b1 = (const float*)d_in[3];
    const float* W2 = (const float*)d_in[4];
    const float* b2 = (const float*)d_in[5];
    float* out = (float*)d_out;

    __half* Z;  cudaGetSymbolAddress((void**)&Z,   g_Z);
    float* H1;  cudaGetSymbolAddress((void**)&H1,  g_H1);
    int*   cnt; cudaGetSymbolAddress((void**)&cnt, g_cnt);

    cudaMemsetAsync(cnt, 0, N * sizeof(int));

    // gemm1 (blocks 0..511, start immediately) + extract CSR (blocks 512..8703)
    fused_extract_gemm_kernel<<<GEMM_GRID + 8192, 256>>>(A, X, W1, Z);

    spmm_kernel<<<1024, 256>>>(Z, b1, H1);    // H1 = relu(An@(X@W1) + b1)
    gemm_kernel<<<GEMM_GRID, 256>>>(H1, W2, Z);
    spmm_kernel<<<1024, 256>>>(Z, b2, out);   // out = relu(An@(H1@W2) + b2)
}

// round 9
// speedup vs baseline: 1.2983x; 1.0672x over previous
#include <cuda_runtime.h>
#include <cuda_bf16.h>
#include <cuda_fp16.h>
#include <cstdint>

#define N 8192
#define F 128
#define CSRW 128        // fixed CSR row width; max in-degree ~60 for Binomial(8192, 32/8192)
#define GEMM_ROWS 16    // rows per gemm block
#define GEMM_GRID (N / GEMM_ROWS)   // 512
#define XS_STRIDE 18    // even => 8B-aligned LDS.64 reads; 2-way conflict on fill only

// ---------------- scratch (static device globals; no allocation) ----------
__device__ __half g_Z[N * F];       // UNscaled GEMM output, fp16 (SpMM gather input)
__device__ float  g_H1[N * F];      // layer-1 activation (fp32, gemm2 input)
__device__ int    g_cnt[N];         // in-degree per dst (col-sums of A)
__device__ float  g_dis[N];         // D^{-1/2} table (precomputed after extract)
__device__ int    g_csr[N * CSRW];  // fixed-slot CSR: row i at [i*CSRW, i*CSRW+cnt[i])

// ---------------- f32x2 packed helpers ------------------------------------
__device__ __forceinline__ uint64_t pk2(float lo, float hi) {
    uint64_t r;
    asm("mov.b64 %0, {%1, %2};" : "=l"(r) : "f"(lo), "f"(hi));
    return r;
}
__device__ __forceinline__ uint64_t fma2(uint64_t a, uint64_t b, uint64_t c) {
    uint64_t d;
    asm("fma.rn.f32x2 %0, %1, %2, %3;" : "=l"(d) : "l"(a), "l"(b), "l"(c));
    return d;
}
__device__ __forceinline__ void upk2(uint64_t v, float& lo, float& hi) {
    asm("mov.b64 {%0, %1}, %2;" : "=f"(lo), "=f"(hi) : "l"(v));
}

// -------- gemm body: out[r,:] = half(M[r,:] @ W)  (unscaled, fp16 out) -----
__device__ __forceinline__ void gemm_body_h(const float* __restrict__ M,
                                            const float* __restrict__ W,
                                            __half* __restrict__ out,
                                            int rowBase, int tid,
                                            float* Xs /* 128*XS_STRIDE */) {
    #pragma unroll
    for (int it = 0; it < 8; it++) {
        int idx = tid + 256 * it;        // 2048 elements
        int r = idx >> 7;                // 0..15
        int k = idx & 127;
        Xs[k * XS_STRIDE + r] = M[(rowBase + r) * F + k];
    }
    __syncthreads();

    const float4* W4 = (const float4*)W;
    int cg = tid & 31;           // cols [4cg, 4cg+4)
    int rp = tid >> 5;           // 0..7 -> rows 2rp, 2rp+1

    uint64_t acc[4];
    #pragma unroll
    for (int c = 0; c < 4; c++) acc[c] = 0;

    float4 w = W4[cg];           // prefetch k=0
    #pragma unroll 8
    for (int k = 0; k < 128; k++) {
        float4 wc = w;
        if (k < 127) w = W4[(k + 1) * 32 + cg];
        uint64_t xp = *(const uint64_t*)&Xs[k * XS_STRIDE + 2 * rp];  // rows 2rp,2rp+1
        acc[0] = fma2(xp, pk2(wc.x, wc.x), acc[0]);
        acc[1] = fma2(xp, pk2(wc.y, wc.y), acc[1]);
        acc[2] = fma2(xp, pk2(wc.z, wc.z), acc[2]);
        acc[3] = fma2(xp, pk2(wc.w, wc.w), acc[3]);
    }

    float lo[4], hi[4];
    #pragma unroll
    for (int c = 0; c < 4; c++) upk2(acc[c], lo[c], hi[c]);

    uint2* out2 = (uint2*)out;   // 4 halves per uint2; 32 uint2 per row
    int rowA = rowBase + 2 * rp;
    __half2 a01 = __floats2half2_rn(lo[0], lo[1]);
    __half2 a23 = __floats2half2_rn(lo[2], lo[3]);
    __half2 b01 = __floats2half2_rn(hi[0], hi[1]);
    __half2 b23 = __floats2half2_rn(hi[2], hi[3]);
    uint2 va, vb;
    va.x = *(uint32_t*)&a01; va.y = *(uint32_t*)&a23;
    vb.x = *(uint32_t*)&b01; vb.y = *(uint32_t*)&b23;
    out2[rowA * 32 + cg]       = va;
    out2[(rowA + 1) * 32 + cg] = vb;
}

// ---------------- extract body (one pass over A slice, streaming) ----------
__device__ __forceinline__ void extract_body(const float* __restrict__ A,
                                             int bid, int tid) {
    const float4* A4 = (const float4*)A;
    int base = bid * 2048;
    #pragma unroll
    for (int s = 0; s < 8; s++) {
        int q = base + tid + 256 * s;
        float4 v = __ldcs(A4 + q);        // evict-first: don't thrash L2
        int idx0 = q * 4;
        float vv[4] = {v.x, v.y, v.z, v.w};
        #pragma unroll
        for (int c = 0; c < 4; c++) {
            if (vv[c] != 0.0f) {
                int idx = idx0 + c;
                int i = idx & (N - 1);   // col = dst
                int j = idx >> 13;       // row = src
                int p = atomicAdd(&g_cnt[i], 1);
                if (p < CSRW) g_csr[i * CSRW + p] = j;
            }
        }
    }
}

// ------- fused: gemm1 (blocks 0..511, dispatched FIRST) + extract ----------
__global__ void __launch_bounds__(256)
fused_extract_gemm_kernel(const float* __restrict__ A,
                          const float* __restrict__ X,
                          const float* __restrict__ W1,
                          __half* __restrict__ Z) {
    __shared__ float Xs[128 * XS_STRIDE];
    int b = blockIdx.x;
    if (b < GEMM_GRID) {
        gemm_body_h(X, W1, Z, b * GEMM_ROWS, threadIdx.x, Xs);
    } else {
        extract_body(A, b - GEMM_GRID, threadIdx.x);
    }
}

// ---------------- dis table: g_dis[i] = rsqrt(cnt[i]+1) --------------------
__global__ void dis_kernel() {
    int t = blockIdx.x * 1024 + threadIdx.x;
    g_dis[t] = rsqrtf((float)g_cnt[t] + 1.0f);
}

// ---------------- standalone gemm (layer 2) --------------------------------
__global__ void __launch_bounds__(256)
gemm_kernel(const float* __restrict__ M, const float* __restrict__ W,
            __half* __restrict__ out) {
    __shared__ float Xs[128 * XS_STRIDE];
    gemm_body_h(M, W, out, blockIdx.x * GEMM_ROWS, threadIdx.x, Xs);
}

// ---- SpMM fp16-gather: one warp per dst row; lane owns 4 features ---------
// out[i,:] = relu(dis_i*(dis_i*Z[i,:] + sum_j dis_j*Z[j,:]) + b), fp32 accumulate
__global__ void __launch_bounds__(256)
spmm_kernel(const __half* __restrict__ Z,
            const float* __restrict__ bias,
            float* __restrict__ out) {
    __shared__ int   sidx[8][CSRW];   // uint2-row offsets (src*32)
    __shared__ float sdis[8][CSRW];
    int warp = threadIdx.x >> 5;
    int lane = threadIdx.x & 31;
    int i = blockIdx.x * 8 + warp;

    int cnt = g_cnt[i];
    int m = cnt < CSRW ? cnt : CSRW;

    for (int e = lane; e < m; e += 32) {
        int s = g_csr[i * CSRW + e];
        sidx[warp][e] = s * 32;
        sdis[warp][e] = g_dis[s];         // precomputed table (L2-hot)
    }
    __syncwarp();

    const uint2* Z2 = (const uint2*)Z;   // 4 halves per element
    float dis_i = g_dis[i];
    uint64_t di = pk2(dis_i, dis_i);

    uint2 self = Z2[i * 32 + lane];
    float2 sa = __half22float2(*(const __half2*)&self.x);
    float2 sb = __half22float2(*(const __half2*)&self.y);
    uint64_t acc0 = fma2(pk2(sa.x, sa.y), di, 0ull);
    uint64_t acc1 = fma2(pk2(sb.x, sb.y), di, 0ull);

    int e = 0;
    for (; e + 8 <= m; e += 8) {
        uint2 u[8];
        #pragma unroll
        for (int q = 0; q < 8; q++) u[q] = Z2[sidx[warp][e + q] + lane];
        #pragma unroll
        for (int q = 0; q < 8; q++) {
            float d = sdis[warp][e + q];
            uint64_t dd = pk2(d, d);
            float2 fa = __half22float2(*(const __half2*)&u[q].x);
            float2 fb = __half22float2(*(const __half2*)&u[q].y);
            acc0 = fma2(pk2(fa.x, fa.y), dd, acc0);
            acc1 = fma2(pk2(fb.x, fb.y), dd, acc1);
        }
    }
    for (; e < m; e++) {
        uint2 u = Z2[sidx[warp][e] + lane];
        float d = sdis[warp][e];
        uint64_t dd = pk2(d, d);
        float2 fa = __half22float2(*(const __half2*)&u.x);
        float2 fb = __half22float2(*(const __half2*)&u.y);
        acc0 = fma2(pk2(fa.x, fa.y), dd, acc0);
        acc1 = fma2(pk2(fb.x, fb.y), dd, acc1);
    }

    float a0, a1, a2, a3;
    upk2(acc0, a0, a1);
    upk2(acc1, a2, a3);
    float4 b4 = ((const float4*)bias)[lane];
    float4 r;
    r.x = fmaxf(dis_i * a0 + b4.x, 0.0f);
    r.y = fmaxf(dis_i * a1 + b4.y, 0.0f);
    r.z = fmaxf(dis_i * a2 + b4.z, 0.0f);
    r.w = fmaxf(dis_i * a3 + b4.w, 0.0f);
    ((float4*)out)[i * 32 + lane] = r;
}

// ---------------- launch ---------------------------------------------------
extern "C" void kernel_launch(void* const* d_in, const int* in_sizes, int n_in,
                              void* d_out, int out_size) {
    const float* X  = (const float*)d_in[0];
    const float* A  = (const float*)d_in[1];
    const float* W1 = (const float*)d_in[2];
    const float* b1 = (const float*)d_in[3];
    const float* W2 = (const float*)d_in[4];
    const float* b2 = (const float*)d_in[5];
    float* out = (float*)d_out;

    __half* Z;  cudaGetSymbolAddress((void**)&Z,   g_Z);
    float* H1;  cudaGetSymbolAddress((void**)&H1,  g_H1);
    int*   cnt; cudaGetSymbolAddress((void**)&cnt, g_cnt);

    cudaMemsetAsync(cnt, 0, N * sizeof(int));

    // gemm1 (blocks 0..511, start immediately) + extract CSR (blocks 512..8703)
    fused_extract_gemm_kernel<<<GEMM_GRID + 8192, 256>>>(A, X, W1, Z);
    dis_kernel<<<8, 1024>>>();                // D^{-1/2} table

    spmm_kernel<<<1024, 256>>>(Z, b1, H1);    // H1 = relu(An@(X@W1) + b1)
    gemm_kernel<<<GEMM_GRID, 256>>>(H1, W2, Z);
    spmm_kernel<<<1024, 256>>>(Z, b2, out);   // out = relu(An@(H1@W2) + b2)
}

// round 10
// speedup vs baseline: 1.4218x; 1.0951x over previous
#include <cuda_runtime.h>
#include <cuda_bf16.h>
#include <cuda_fp16.h>
#include <cstdint>

#define N 8192
#define F 128
#define CSRW 128        // fixed CSR row width; max in-degree ~60 for Binomial(8192, 32/8192)
#define GEMM_ROWS 16    // rows per fused gemm1 block
#define GEMM_GRID (N / GEMM_ROWS)   // 512
#define XS_STRIDE 18

// ---------------- scratch (static device globals; no allocation) ----------
__device__ __half g_Z[N * F];       // UNscaled GEMM output, fp16 (SpMM gather input)
__device__ __half g_H1[N * F];      // layer-1 activation, fp16 (hgemm input)
__device__ __half g_W2h[F * F];     // W2 in fp16 [k][n]
__device__ int    g_cnt[N];         // in-degree per dst
__device__ float  g_dis[N];         // D^{-1/2} table
__device__ int    g_csr[N * CSRW];  // fixed-slot CSR

// ---------------- f32x2 packed helpers ------------------------------------
__device__ __forceinline__ uint64_t pk2(float lo, float hi) {
    uint64_t r;
    asm("mov.b64 %0, {%1, %2};" : "=l"(r) : "f"(lo), "f"(hi));
    return r;
}
__device__ __forceinline__ uint64_t fma2(uint64_t a, uint64_t b, uint64_t c) {
    uint64_t d;
    asm("fma.rn.f32x2 %0, %1, %2, %3;" : "=l"(d) : "l"(a), "l"(b), "l"(c));
    return d;
}
__device__ __forceinline__ void upk2(uint64_t v, float& lo, float& hi) {
    asm("mov.b64 {%0, %1}, %2;" : "=f"(lo), "=f"(hi) : "l"(v));
}

// -------- scalar gemm body for layer 1 (fused under extract; fp16 out) -----
__device__ __forceinline__ void gemm_body_h(const float* __restrict__ M,
                                            const float* __restrict__ W,
                                            __half* __restrict__ out,
                                            int rowBase, int tid,
                                            float* Xs) {
    #pragma unroll
    for (int it = 0; it < 8; it++) {
        int idx = tid + 256 * it;
        int r = idx >> 7;
        int k = idx & 127;
        Xs[k * XS_STRIDE + r] = M[(rowBase + r) * F + k];
    }
    __syncthreads();

    const float4* W4 = (const float4*)W;
    int cg = tid & 31;
    int rp = tid >> 5;

    uint64_t acc[4];
    #pragma unroll
    for (int c = 0; c < 4; c++) acc[c] = 0;

    float4 w = W4[cg];
    #pragma unroll 8
    for (int k = 0; k < 128; k++) {
        float4 wc = w;
        if (k < 127) w = W4[(k + 1) * 32 + cg];
        uint64_t xp = *(const uint64_t*)&Xs[k * XS_STRIDE + 2 * rp];
        acc[0] = fma2(xp, pk2(wc.x, wc.x), acc[0]);
        acc[1] = fma2(xp, pk2(wc.y, wc.y), acc[1]);
        acc[2] = fma2(xp, pk2(wc.z, wc.z), acc[2]);
        acc[3] = fma2(xp, pk2(wc.w, wc.w), acc[3]);
    }

    float lo[4], hi[4];
    #pragma unroll
    for (int c = 0; c < 4; c++) upk2(acc[c], lo[c], hi[c]);

    uint2* out2 = (uint2*)out;
    int rowA = rowBase + 2 * rp;
    __half2 a01 = __floats2half2_rn(lo[0], lo[1]);
    __half2 a23 = __floats2half2_rn(lo[2], lo[3]);
    __half2 b01 = __floats2half2_rn(hi[0], hi[1]);
    __half2 b23 = __floats2half2_rn(hi[2], hi[3]);
    uint2 va, vb;
    va.x = *(uint32_t*)&a01; va.y = *(uint32_t*)&a23;
    vb.x = *(uint32_t*)&b01; vb.y = *(uint32_t*)&b23;
    out2[rowA * 32 + cg]       = va;
    out2[(rowA + 1) * 32 + cg] = vb;
}

// ---------------- extract body (one pass over A slice, streaming) ----------
__device__ __forceinline__ void extract_body(const float* __restrict__ A,
                                             int bid, int tid) {
    const float4* A4 = (const float4*)A;
    int base = bid * 2048;
    #pragma unroll
    for (int s = 0; s < 8; s++) {
        int q = base + tid + 256 * s;
        float4 v = __ldcs(A4 + q);
        int idx0 = q * 4;
        float vv[4] = {v.x, v.y, v.z, v.w};
        #pragma unroll
        for (int c = 0; c < 4; c++) {
            if (vv[c] != 0.0f) {
                int idx = idx0 + c;
                int i = idx & (N - 1);
                int j = idx >> 13;
                int p = atomicAdd(&g_cnt[i], 1);
                if (p < CSRW) g_csr[i * CSRW + p] = j;
            }
        }
    }
}

// ------- fused: gemm1 (blocks 0..511, dispatched FIRST) + extract ----------
__global__ void __launch_bounds__(256)
fused_extract_gemm_kernel(const float* __restrict__ A,
                          const float* __restrict__ X,
                          const float* __restrict__ W1,
                          __half* __restrict__ Z) {
    __shared__ float Xs[128 * XS_STRIDE];
    int b = blockIdx.x;
    if (b < GEMM_GRID) {
        gemm_body_h(X, W1, Z, b * GEMM_ROWS, threadIdx.x, Xs);
    } else {
        extract_body(A, b - GEMM_GRID, threadIdx.x);
    }
}

// -------- prep: dis table + W2 -> fp16 (grid 16 x 1024 = 16384) ------------
__global__ void prep_kernel(const float* __restrict__ W2) {
    int t = blockIdx.x * 1024 + threadIdx.x;
    if (t < N) g_dis[t] = rsqrtf((float)g_cnt[t] + 1.0f);
    g_W2h[t] = __float2half(W2[t]);
}

// -------- HMMA gemm2: Z[32-row tile] = H1h @ W2h (fp16 in, fp32 acc) -------
// 256 blocks x 128 threads. Block tile 32x128; warp tile 32x32.
#define BP 136   // smem pitch in halves (row stride 272B: conflict-free ldmatrix)
__global__ void __launch_bounds__(128)
hgemm_kernel(const __half* __restrict__ Ag,   // [N,128] fp16
             __half* __restrict__ outg) {     // [N,128] fp16
    __shared__ __align__(16) __half As[32 * BP];
    __shared__ __align__(16) __half Bs[128 * BP];
    int tid = threadIdx.x;
    int rowBase = blockIdx.x * 32;

    // Load A tile (32x128) and full B (128x128) into padded smem.
    const uint4* A4 = (const uint4*)(Ag + rowBase * F);
    #pragma unroll
    for (int it = 0; it < 4; it++) {
        int idx = tid + 128 * it;           // 512 uint4
        int r = idx >> 4, c8 = idx & 15;
        *(uint4*)&As[r * BP + c8 * 8] = A4[idx];
    }
    const uint4* B4 = (const uint4*)g_W2h;
    #pragma unroll
    for (int it = 0; it < 16; it++) {
        int idx = tid + 128 * it;           // 2048 uint4
        int r = idx >> 4, c8 = idx & 15;
        *(uint4*)&Bs[r * BP + c8 * 8] = B4[idx];
    }
    __syncthreads();

    int warp = tid >> 5, lane = tid & 31;
    int n0 = warp * 32;

    float c[2][4][4];
    #pragma unroll
    for (int mt = 0; mt < 2; mt++)
        #pragma unroll
        for (int nb = 0; nb < 4; nb++)
            #pragma unroll
            for (int q = 0; q < 4; q++) c[mt][nb][q] = 0.0f;

    unsigned aBase = (unsigned)__cvta_generic_to_shared(As);
    unsigned bBase = (unsigned)__cvta_generic_to_shared(Bs);
    int lr = lane & 15, lc = lane >> 4;     // ldmatrix addressing

    #pragma unroll
    for (int kc = 0; kc < 8; kc++) {
        uint32_t a[2][4];
        #pragma unroll
        for (int mt = 0; mt < 2; mt++) {
            unsigned addr = aBase + (((mt * 16 + lr) * BP + kc * 16 + lc * 8) << 1);
            asm volatile("ldmatrix.sync.aligned.m8n8.x4.shared.b16 {%0,%1,%2,%3}, [%4];"
                         : "=r"(a[mt][0]), "=r"(a[mt][1]), "=r"(a[mt][2]), "=r"(a[mt][3])
                         : "r"(addr));
        }
        uint32_t b[2][4];
        #pragma unroll
        for (int nt = 0; nt < 2; nt++) {
            unsigned addr = bBase + (((kc * 16 + lr) * BP + n0 + nt * 16 + lc * 8) << 1);
            asm volatile("ldmatrix.sync.aligned.m8n8.x4.trans.shared.b16 {%0,%1,%2,%3}, [%4];"
                         : "=r"(b[nt][0]), "=r"(b[nt][1]), "=r"(b[nt][2]), "=r"(b[nt][3])
                         : "r"(addr));
        }
        #pragma unroll
        for (int mt = 0; mt < 2; mt++)
            #pragma unroll
            for (int nb = 0; nb < 4; nb++) {
                uint32_t b0 = b[nb >> 1][(nb & 1) * 2];
                uint32_t b1 = b[nb >> 1][(nb & 1) * 2 + 1];
                asm volatile(
                    "mma.sync.aligned.m16n8k16.row.col.f32.f16.f16.f32 "
                    "{%0,%1,%2,%3}, {%4,%5,%6,%7}, {%8,%9}, {%0,%1,%2,%3};"
                    : "+f"(c[mt][nb][0]), "+f"(c[mt][nb][1]),
                      "+f"(c[mt][nb][2]), "+f"(c[mt][nb][3])
                    : "r"(a[mt][0]), "r"(a[mt][1]), "r"(a[mt][2]), "r"(a[mt][3]),
                      "r"(b0), "r"(b1));
            }
    }

    // Store: lane l of m16n8 frag: rows l/4 and l/4+8; cols 2(l%4), 2(l%4)+1.
    __half2* O2 = (__half2*)outg;   // 64 half2 per row
    int fr = lane >> 2, fc = lane & 3;
    #pragma unroll
    for (int mt = 0; mt < 2; mt++)
        #pragma unroll
        for (int nb = 0; nb < 4; nb++) {
            int row = rowBase + mt * 16 + fr;
            int col2 = (n0 + nb * 8 + 2 * fc) >> 1;
            O2[row * 64 + col2]       = __floats2half2_rn(c[mt][nb][0], c[mt][nb][1]);
            O2[(row + 8) * 64 + col2] = __floats2half2_rn(c[mt][nb][2], c[mt][nb][3]);
        }
}

// ---- SpMM fp16-gather: one warp per dst row; lane owns 4 features ---------
// out[i,:] = relu(dis_i*(dis_i*Z[i,:] + sum_j dis_j*Z[j,:]) + b), fp32 accumulate
template<bool HOUT>
__global__ void __launch_bounds__(256)
spmm_kernel(const __half* __restrict__ Z,
            const float* __restrict__ bias,
            void* __restrict__ outv) {
    __shared__ int   sidx[8][CSRW];
    __shared__ float sdis[8][CSRW];
    int warp = threadIdx.x >> 5;
    int lane = threadIdx.x & 31;
    int i = blockIdx.x * 8 + warp;

    int cnt = g_cnt[i];
    int m = cnt < CSRW ? cnt : CSRW;

    for (int e = lane; e < m; e += 32) {
        int s = g_csr[i * CSRW + e];
        sidx[warp][e] = s * 32;
        sdis[warp][e] = g_dis[s];
    }
    __syncwarp();

    const uint2* Z2 = (const uint2*)Z;
    float dis_i = g_dis[i];
    uint64_t di = pk2(dis_i, dis_i);

    uint2 self = Z2[i * 32 + lane];
    float2 sa = __half22float2(*(const __half2*)&self.x);
    float2 sb = __half22float2(*(const __half2*)&self.y);
    uint64_t acc0 = fma2(pk2(sa.x, sa.y), di, 0ull);
    uint64_t acc1 = fma2(pk2(sb.x, sb.y), di, 0ull);

    int e = 0;
    for (; e + 8 <= m; e += 8) {
        uint2 u[8];
        #pragma unroll
        for (int q = 0; q < 8; q++) u[q] = Z2[sidx[warp][e + q] + lane];
        #pragma unroll
        for (int q = 0; q < 8; q++) {
            float d = sdis[warp][e + q];
            uint64_t dd = pk2(d, d);
            float2 fa = __half22float2(*(const __half2*)&u[q].x);
            float2 fb = __half22float2(*(const __half2*)&u[q].y);
            acc0 = fma2(pk2(fa.x, fa.y), dd, acc0);
            acc1 = fma2(pk2(fb.x, fb.y), dd, acc1);
        }
    }
    for (; e < m; e++) {
        uint2 u = Z2[sidx[warp][e] + lane];
        float d = sdis[warp][e];
        uint64_t dd = pk2(d, d);
        float2 fa = __half22float2(*(const __half2*)&u.x);
        float2 fb = __half22float2(*(const __half2*)&u.y);
        acc0 = fma2(pk2(fa.x, fa.y), dd, acc0);
        acc1 = fma2(pk2(fb.x, fb.y), dd, acc1);
    }

    float a0, a1, a2, a3;
    upk2(acc0, a0, a1);
    upk2(acc1, a2, a3);
    float4 b4 = ((const float4*)bias)[lane];
    float r0 = fmaxf(dis_i * a0 + b4.x, 0.0f);
    float r1 = fmaxf(dis_i * a1 + b4.y, 0.0f);
    float r2 = fmaxf(dis_i * a2 + b4.z, 0.0f);
    float r3 = fmaxf(dis_i * a3 + b4.w, 0.0f);

    if (HOUT) {
        __half2 h01 = __floats2half2_rn(r0, r1);
        __half2 h23 = __floats2half2_rn(r2, r3);
        uint2 v;
        v.x = *(uint32_t*)&h01; v.y = *(uint32_t*)&h23;
        ((uint2*)outv)[i * 32 + lane] = v;
    } else {
        ((float4*)outv)[i * 32 + lane] = make_float4(r0, r1, r2, r3);
    }
}

// ---------------- launch ---------------------------------------------------
extern "C" void kernel_launch(void* const* d_in, const int* in_sizes, int n_in,
                              void* d_out, int out_size) {
    const float* X  = (const float*)d_in[0];
    const float* A  = (const float*)d_in[1];
    const float* W1 = (const float*)d_in[2];
    const float* b1 = (const float*)d_in[3];
    const float* W2 = (const float*)d_in[4];
    const float* b2 = (const float*)d_in[5];
    float* out = (float*)d_out;

    __half* Z;  cudaGetSymbolAddress((void**)&Z,   g_Z);
    __half* H1; cudaGetSymbolAddress((void**)&H1,  g_H1);
    int*   cnt; cudaGetSymbolAddress((void**)&cnt, g_cnt);

    cudaMemsetAsync(cnt, 0, N * sizeof(int));

    // gemm1 (blocks 0..511, start immediately) + extract CSR (blocks 512..8703)
    fused_extract_gemm_kernel<<<GEMM_GRID + 8192, 256>>>(A, X, W1, Z);
    prep_kernel<<<16, 1024>>>(W2);                  // dis table + W2 fp16

    spmm_kernel<true ><<<1024, 256>>>(Z, b1, H1);   // H1 = relu(An@(X@W1)+b1), fp16
    hgemm_kernel<<<256, 128>>>(H1, Z);              // Z = H1 @ W2  (HMMA)
    spmm_kernel<false><<<1024, 256>>>(Z, b2, out);  // out = relu(An@(H1@W2)+b2)
}

// round 11
// speedup vs baseline: 1.4562x; 1.0243x over previous
#include <cuda_runtime.h>
#include <cuda_bf16.h>
#include <cuda_fp16.h>
#include <cstdint>

#define N 8192
#define F 128
#define CSRW 128        // fixed CSR row width; max in-degree ~60 for Binomial(8192, 32/8192)
#define GEMM_ROWS 16    // rows per fused gemm1 block
#define GEMM_GRID (N / GEMM_ROWS)   // 512
#define XS_STRIDE 18

// ---------------- scratch (static device globals; no allocation) ----------
__device__ __half g_Z[N * F];       // UNscaled GEMM output, fp16 (SpMM gather input)
__device__ __half g_H1[N * F];      // layer-1 activation, fp16 (hgemm input)
__device__ __half g_W2h[F * F];     // W2 in fp16 [k][n]
__device__ int    g_cnt[N];         // in-degree per dst
__device__ float  g_dis[N];         // D^{-1/2} table
__device__ int    g_csr[N * CSRW];  // fixed-slot CSR

// ---------------- f32x2 packed helpers ------------------------------------
__device__ __forceinline__ uint64_t pk2(float lo, float hi) {
    uint64_t r;
    asm("mov.b64 %0, {%1, %2};" : "=l"(r) : "f"(lo), "f"(hi));
    return r;
}
__device__ __forceinline__ uint64_t fma2(uint64_t a, uint64_t b, uint64_t c) {
    uint64_t d;
    asm("fma.rn.f32x2 %0, %1, %2, %3;" : "=l"(d) : "l"(a), "l"(b), "l"(c));
    return d;
}
__device__ __forceinline__ void upk2(uint64_t v, float& lo, float& hi) {
    asm("mov.b64 {%0, %1}, %2;" : "=f"(lo), "=f"(hi) : "l"(v));
}

// -------- scalar gemm body for layer 1 (fused under extract; fp16 out) -----
__device__ __forceinline__ void gemm_body_h(const float* __restrict__ M,
                                            const float* __restrict__ W,
                                            __half* __restrict__ out,
                                            int rowBase, int tid,
                                            float* Xs) {
    #pragma unroll
    for (int it = 0; it < 8; it++) {
        int idx = tid + 256 * it;
        int r = idx >> 7;
        int k = idx & 127;
        Xs[k * XS_STRIDE + r] = M[(rowBase + r) * F + k];
    }
    __syncthreads();

    const float4* W4 = (const float4*)W;
    int cg = tid & 31;
    int rp = tid >> 5;

    uint64_t acc[4];
    #pragma unroll
    for (int c = 0; c < 4; c++) acc[c] = 0;

    float4 w = W4[cg];
    #pragma unroll 8
    for (int k = 0; k < 128; k++) {
        float4 wc = w;
        if (k < 127) w = W4[(k + 1) * 32 + cg];
        uint64_t xp = *(const uint64_t*)&Xs[k * XS_STRIDE + 2 * rp];
        acc[0] = fma2(xp, pk2(wc.x, wc.x), acc[0]);
        acc[1] = fma2(xp, pk2(wc.y, wc.y), acc[1]);
        acc[2] = fma2(xp, pk2(wc.z, wc.z), acc[2]);
        acc[3] = fma2(xp, pk2(wc.w, wc.w), acc[3]);
    }

    float lo[4], hi[4];
    #pragma unroll
    for (int c = 0; c < 4; c++) upk2(acc[c], lo[c], hi[c]);

    uint2* out2 = (uint2*)out;
    int rowA = rowBase + 2 * rp;
    __half2 a01 = __floats2half2_rn(lo[0], lo[1]);
    __half2 a23 = __floats2half2_rn(lo[2], lo[3]);
    __half2 b01 = __floats2half2_rn(hi[0], hi[1]);
    __half2 b23 = __floats2half2_rn(hi[2], hi[3]);
    uint2 va, vb;
    va.x = *(uint32_t*)&a01; va.y = *(uint32_t*)&a23;
    vb.x = *(uint32_t*)&b01; vb.y = *(uint32_t*)&b23;
    out2[rowA * 32 + cg]       = va;
    out2[(rowA + 1) * 32 + cg] = vb;
}

// -------- extract body v2: register-batched loads + integer tests ----------
__device__ __forceinline__ void extract_body(const float* __restrict__ A,
                                             int bid, int tid) {
    const uint4* A4 = (const uint4*)A;
    int base = bid * 2048 + tid;
    uint4 u[8];
    #pragma unroll
    for (int s = 0; s < 8; s++) u[s] = __ldcs(A4 + base + 256 * s);  // MLP=8
    #pragma unroll
    for (int s = 0; s < 8; s++) {
        if (u[s].x | u[s].y | u[s].z | u[s].w) {   // A is exactly 0.0f/1.0f
            int idx0 = (base + 256 * s) * 4;
            uint32_t w[4] = {u[s].x, u[s].y, u[s].z, u[s].w};
            #pragma unroll
            for (int c = 0; c < 4; c++) {
                if (w[c]) {
                    int idx = idx0 + c;
                    int i = idx & (N - 1);   // col = dst
                    int j = idx >> 13;       // row = src
                    int p = atomicAdd(&g_cnt[i], 1);
                    if (p < CSRW) g_csr[i * CSRW + p] = j;
                }
            }
        }
    }
}

// ------- fused: gemm1 (blocks 0..511, dispatched FIRST) + extract ----------
__global__ void __launch_bounds__(256)
fused_extract_gemm_kernel(const float* __restrict__ A,
                          const float* __restrict__ X,
                          const float* __restrict__ W1,
                          __half* __restrict__ Z) {
    __shared__ float Xs[128 * XS_STRIDE];
    int b = blockIdx.x;
    if (b < GEMM_GRID) {
        gemm_body_h(X, W1, Z, b * GEMM_ROWS, threadIdx.x, Xs);
    } else {
        extract_body(A, b - GEMM_GRID, threadIdx.x);
    }
}

// -------- prep: dis table + W2 -> fp16 (grid 16 x 1024 = 16384) ------------
__global__ void prep_kernel(const float* __restrict__ W2) {
    int t = blockIdx.x * 1024 + threadIdx.x;
    if (t < N) g_dis[t] = rsqrtf((float)g_cnt[t] + 1.0f);
    g_W2h[t] = __float2half(W2[t]);
}

// -------- HMMA gemm2: Z[32-row tile] = H1h @ W2h (fp16 in, fp32 acc) -------
#define BP 136   // smem pitch in halves (row stride 272B: conflict-free ldmatrix)
__global__ void __launch_bounds__(128)
hgemm_kernel(const __half* __restrict__ Ag,   // [N,128] fp16
             __half* __restrict__ outg) {     // [N,128] fp16
    __shared__ __align__(16) __half As[32 * BP];
    __shared__ __align__(16) __half Bs[128 * BP];
    int tid = threadIdx.x;
    int rowBase = blockIdx.x * 32;

    const uint4* A4 = (const uint4*)(Ag + rowBase * F);
    #pragma unroll
    for (int it = 0; it < 4; it++) {
        int idx = tid + 128 * it;
        int r = idx >> 4, c8 = idx & 15;
        *(uint4*)&As[r * BP + c8 * 8] = A4[idx];
    }
    const uint4* B4 = (const uint4*)g_W2h;
    #pragma unroll
    for (int it = 0; it < 16; it++) {
        int idx = tid + 128 * it;
        int r = idx >> 4, c8 = idx & 15;
        *(uint4*)&Bs[r * BP + c8 * 8] = B4[idx];
    }
    __syncthreads();

    int warp = tid >> 5, lane = tid & 31;
    int n0 = warp * 32;

    float c[2][4][4];
    #pragma unroll
    for (int mt = 0; mt < 2; mt++)
        #pragma unroll
        for (int nb = 0; nb < 4; nb++)
            #pragma unroll
            for (int q = 0; q < 4; q++) c[mt][nb][q] = 0.0f;

    unsigned aBase = (unsigned)__cvta_generic_to_shared(As);
    unsigned bBase = (unsigned)__cvta_generic_to_shared(Bs);
    int lr = lane & 15, lc = lane >> 4;

    #pragma unroll
    for (int kc = 0; kc < 8; kc++) {
        uint32_t a[2][4];
        #pragma unroll
        for (int mt = 0; mt < 2; mt++) {
            unsigned addr = aBase + (((mt * 16 + lr) * BP + kc * 16 + lc * 8) << 1);
            asm volatile("ldmatrix.sync.aligned.m8n8.x4.shared.b16 {%0,%1,%2,%3}, [%4];"
                         : "=r"(a[mt][0]), "=r"(a[mt][1]), "=r"(a[mt][2]), "=r"(a[mt][3])
                         : "r"(addr));
        }
        uint32_t b[2][4];
        #pragma unroll
        for (int nt = 0; nt < 2; nt++) {
            unsigned addr = bBase + (((kc * 16 + lr) * BP + n0 + nt * 16 + lc * 8) << 1);
            asm volatile("ldmatrix.sync.aligned.m8n8.x4.trans.shared.b16 {%0,%1,%2,%3}, [%4];"
                         : "=r"(b[nt][0]), "=r"(b[nt][1]), "=r"(b[nt][2]), "=r"(b[nt][3])
                         : "r"(addr));
        }
        #pragma unroll
        for (int mt = 0; mt < 2; mt++)
            #pragma unroll
            for (int nb = 0; nb < 4; nb++) {
                uint32_t b0 = b[nb >> 1][(nb & 1) * 2];
                uint32_t b1 = b[nb >> 1][(nb & 1) * 2 + 1];
                asm volatile(
                    "mma.sync.aligned.m16n8k16.row.col.f32.f16.f16.f32 "
                    "{%0,%1,%2,%3}, {%4,%5,%6,%7}, {%8,%9}, {%0,%1,%2,%3};"
                    : "+f"(c[mt][nb][0]), "+f"(c[mt][nb][1]),
                      "+f"(c[mt][nb][2]), "+f"(c[mt][nb][3])
                    : "r"(a[mt][0]), "r"(a[mt][1]), "r"(a[mt][2]), "r"(a[mt][3]),
                      "r"(b0), "r"(b1));
            }
    }

    __half2* O2 = (__half2*)outg;
    int fr = lane >> 2, fc = lane & 3;
    #pragma unroll
    for (int mt = 0; mt < 2; mt++)
        #pragma unroll
        for (int nb = 0; nb < 4; nb++) {
            int row = rowBase + mt * 16 + fr;
            int col2 = (n0 + nb * 8 + 2 * fc) >> 1;
            O2[row * 64 + col2]       = __floats2half2_rn(c[mt][nb][0], c[mt][nb][1]);
            O2[(row + 8) * 64 + col2] = __floats2half2_rn(c[mt][nb][2], c[mt][nb][3]);
        }
}

// ---- SpMM v2: 2 warps per dst row (halved serial latency); lane = 4 feats -
// out[i,:] = relu(dis_i*(dis_i*Z[i,:] + sum_j dis_j*Z[j,:]) + b), fp32 accumulate
template<bool HOUT>
__global__ void __launch_bounds__(256)
spmm_kernel(const __half* __restrict__ Z,
            const float* __restrict__ bias,
            void* __restrict__ outv) {
    __shared__ int    sidx[4][CSRW];
    __shared__ float  sdis[4][CSRW];
    __shared__ float4 pacc[4][32];
    int warp = threadIdx.x >> 5;
    int lane = threadIdx.x & 31;
    int r = warp >> 1;      // local row 0..3
    int h = warp & 1;       // half 0/1
    int i = blockIdx.x * 4 + r;
    int barid = r + 1;      // pair-scoped named barrier

    int cnt = g_cnt[i];
    int m = cnt < CSRW ? cnt : CSRW;

    // both warps of the pair stage cooperatively
    for (int e = h * 32 + lane; e < m; e += 64) {
        int s = g_csr[i * CSRW + e];
        sidx[r][e] = s * 32;
        sdis[r][e] = g_dis[s];
    }
    asm volatile("bar.sync %0, 64;" :: "r"(barid) : "memory");

    int mh = (m + 1) >> 1;
    int e0 = h ? mh : 0;
    int e1 = h ? m : mh;

    const uint2* Z2 = (const uint2*)Z;
    float dis_i = g_dis[i];
    uint64_t acc0 = 0, acc1 = 0;
    if (h == 0) {   // self-loop term
        uint2 self = Z2[i * 32 + lane];
        float2 sa = __half22float2(*(const __half2*)&self.x);
        float2 sb = __half22float2(*(const __half2*)&self.y);
        uint64_t di = pk2(dis_i, dis_i);
        acc0 = fma2(pk2(sa.x, sa.y), di, acc0);
        acc1 = fma2(pk2(sb.x, sb.y), di, acc1);
    }

    int e = e0;
    for (; e + 8 <= e1; e += 8) {
        uint2 u[8];
        #pragma unroll
        for (int q = 0; q < 8; q++) u[q] = Z2[sidx[r][e + q] + lane];
        #pragma unroll
        for (int q = 0; q < 8; q++) {
            float d = sdis[r][e + q];
            uint64_t dd = pk2(d, d);
            float2 fa = __half22float2(*(const __half2*)&u[q].x);
            float2 fb = __half22float2(*(const __half2*)&u[q].y);
            acc0 = fma2(pk2(fa.x, fa.y), dd, acc0);
            acc1 = fma2(pk2(fb.x, fb.y), dd, acc1);
        }
    }
    for (; e < e1; e++) {
        uint2 u = Z2[sidx[r][e] + lane];
        float d = sdis[r][e];
        uint64_t dd = pk2(d, d);
        float2 fa = __half22float2(*(const __half2*)&u.x);
        float2 fb = __half22float2(*(const __half2*)&u.y);
        acc0 = fma2(pk2(fa.x, fa.y), dd, acc0);
        acc1 = fma2(pk2(fb.x, fb.y), dd, acc1);
    }

    float a0, a1, a2, a3;
    upk2(acc0, a0, a1);
    upk2(acc1, a2, a3);
    if (h == 1) pacc[r][lane] = make_float4(a0, a1, a2, a3);
    asm volatile("bar.sync %0, 64;" :: "r"(barid) : "memory");

    if (h == 0) {
        float4 p = pacc[r][lane];
        a0 += p.x; a1 += p.y; a2 += p.z; a3 += p.w;
        float4 b4 = ((const float4*)bias)[lane];
        float r0 = fmaxf(dis_i * a0 + b4.x, 0.0f);
        float r1 = fmaxf(dis_i * a1 + b4.y, 0.0f);
        float r2 = fmaxf(dis_i * a2 + b4.z, 0.0f);
        float r3 = fmaxf(dis_i * a3 + b4.w, 0.0f);
        if (HOUT) {
            __half2 h01 = __floats2half2_rn(r0, r1);
            __half2 h23 = __floats2half2_rn(r2, r3);
            uint2 v;
            v.x = *(uint32_t*)&h01; v.y = *(uint32_t*)&h23;
            ((uint2*)outv)[i * 32 + lane] = v;
        } else {
            ((float4*)outv)[i * 32 + lane] = make_float4(r0, r1, r2, r3);
        }
    }
}

// ---------------- launch ---------------------------------------------------
extern "C" void kernel_launch(void* const* d_in, const int* in_sizes, int n_in,
                              void* d_out, int out_size) {
    const float* X  = (const float*)d_in[0];
    const float* A  = (const float*)d_in[1];
    const float* W1 = (const float*)d_in[2];
    const float* b1 = (const float*)d_in[3];
    const float* W2 = (const float*)d_in[4];
    const float* b2 = (const float*)d_in[5];
    float* out = (float*)d_out;

    __half* Z;  cudaGetSymbolAddress((void**)&Z,   g_Z);
    __half* H1; cudaGetSymbolAddress((void**)&H1,  g_H1);
    int*   cnt; cudaGetSymbolAddress((void**)&cnt, g_cnt);

    cudaMemsetAsync(cnt, 0, N * sizeof(int));

    // gemm1 (blocks 0..511, start immediately) + extract CSR (blocks 512..8703)
    fused_extract_gemm_kernel<<<GEMM_GRID + 8192, 256>>>(A, X, W1, Z);
    prep_kernel<<<16, 1024>>>(W2);                  // dis table + W2 fp16

    spmm_kernel<true ><<<2048, 256>>>(Z, b1, H1);   // H1 = relu(An@(X@W1)+b1), fp16
    hgemm_kernel<<<256, 128>>>(H1, Z);              // Z = H1 @ W2  (HMMA)
    spmm_kernel<false><<<2048, 256>>>(Z, b2, out);  // out = relu(An@(H1@W2)+b2)
}